// round 1
// baseline (speedup 1.0000x reference)
#include <cuda_runtime.h>
#include <math.h>

#define SEQ   4096
#define BVAL  8
#define DIMV  512
#define HEADS 8
#define DHV   64
#define MF    266
#define NB    (BVAL*HEADS)     /* 64 batches (b,h) */
#define NROWS (BVAL*SEQ)       /* 32768 */
#define FFD   2048

#define RATIO 0.06131393f      /* 266^-0.5 */
#define DN    0.35355339059327373f /* 64^-0.25 */

// ----------------------------- scratch ------------------------------------
static __device__ float g_h   [(size_t)NROWS*DIMV];
static __device__ float g_q   [(size_t)NROWS*DIMV];
static __device__ float g_k   [(size_t)NROWS*DIMV];
static __device__ float g_v   [(size_t)NROWS*DIMV];
static __device__ float g_attn[(size_t)NROWS*DIMV];
static __device__ float g_x1  [(size_t)NROWS*DIMV];
static __device__ float g_ff1 [(size_t)NROWS*FFD];
static __device__ float g_qd  [(size_t)NB*SEQ*MF];
static __device__ float g_kd  [(size_t)NB*SEQ*MF];
static __device__ float g_projT[DHV*MF];
static __device__ float g_kpsum[NB*MF];
static __device__ float g_ctx  [NB*MF*DHV];
static __device__ float g_dinv [(size_t)NB*SEQ];
static __device__ float g_kmax;

// ----------------------------- helpers ------------------------------------
__device__ __forceinline__ float wredsum(float v){
    #pragma unroll
    for (int o=16;o;o>>=1) v += __shfl_xor_sync(0xffffffffu, v, o);
    return v;
}
__device__ __forceinline__ float wredmax(float v){
    #pragma unroll
    for (int o=16;o;o>>=1) v = fmaxf(v, __shfl_xor_sync(0xffffffffu, v, o));
    return v;
}
__device__ void atomicMaxF(float* addr, float val){
    int old = __float_as_int(*addr);
    while (__int_as_float(old) < val){
        int prev = atomicCAS((int*)addr, old, __float_as_int(val));
        if (prev == old) break;
        old = prev;
    }
}

// ----------------------------- init ---------------------------------------
__global__ void init_kernel(const float* __restrict__ proj){
    int t = blockIdx.x*256 + threadIdx.x;
    if (t == 0) g_kmax = -1e30f;
    if (t < DHV*MF){
        int d = t / MF, m = t % MF;
        g_projT[t] = proj[m*DHV + d] * DN;
    }
    if (t < NB*MF) g_kpsum[t] = 0.f;
}

// ----------------------------- layernorm ----------------------------------
__global__ void ln_kernel(const float* __restrict__ x, const float* __restrict__ g,
                          const float* __restrict__ b, float* __restrict__ out){
    __shared__ float red[8];
    long long row = blockIdx.x;
    const float* xr = x + row*DIMV;
    int t = threadIdx.x;
    float v0 = xr[t], v1 = xr[t+256];
    float s = wredsum(v0+v1);
    if ((t&31)==0) red[t>>5] = s;
    __syncthreads();
    float mu = 0.f;
    #pragma unroll
    for (int i=0;i<8;i++) mu += red[i];
    mu *= (1.f/DIMV);
    __syncthreads();
    float d0 = v0-mu, d1 = v1-mu;
    float vs = wredsum(d0*d0 + d1*d1);
    if ((t&31)==0) red[t>>5] = vs;
    __syncthreads();
    float var = 0.f;
    #pragma unroll
    for (int i=0;i<8;i++) var += red[i];
    var *= (1.f/DIMV);
    float inv = rsqrtf(var + 1e-5f);
    out[row*DIMV + t]       = d0*inv*g[t]     + b[t];
    out[row*DIMV + t + 256] = d1*inv*g[t+256] + b[t+256];
}

// ----------------------------- SGEMM --------------------------------------
// C[M,N] = A(MxK or, TRANSA, KxM) * B[K,N]; batched via blockIdx.z with
// (outer = z/8, inner = z%8) stride decomposition for all pointers.
// EPI: 0 none, 1 bias+residual, 2 bias+exact GELU, 3 per-row scale.
template<int BM,int BN,int BK,int TM,int TN,int EPI,bool TRANSA>
__global__ void __launch_bounds__(256) gemm_k(
    const float* __restrict__ A, const float* __restrict__ B, float* __restrict__ C,
    int M, int N, int K, int lda, int ldb, int ldc,
    long long sAo, long long sAi, long long sBo, long long sBi,
    long long sCo, long long sCi,
    const float* __restrict__ bias,
    const float* __restrict__ res,
    const float* __restrict__ rs, long long sRo, long long sRi)
{
    constexpr int THREADS = (BM/TM)*(BN/TN);
    int z = blockIdx.z;
    A += (long long)(z>>3)*sAo + (long long)(z&7)*sAi;
    B += (long long)(z>>3)*sBo + (long long)(z&7)*sBi;
    C += (long long)(z>>3)*sCo + (long long)(z&7)*sCi;
    const float* rsp = nullptr;
    if (EPI==3) rsp = rs + (long long)(z>>3)*sRo + (long long)(z&7)*sRi;

    __shared__ float As[BK][BM];
    __shared__ float Bs[BK][BN];

    int tid  = threadIdx.x;
    int tcol = tid % (BN/TN);
    int trow = tid / (BN/TN);
    int m0 = blockIdx.y * BM;
    int n0 = blockIdx.x * BN;

    float acc[TM][TN];
    #pragma unroll
    for (int i=0;i<TM;i++)
        #pragma unroll
        for (int j=0;j<TN;j++) acc[i][j] = 0.f;

    for (int k0 = 0; k0 < K; k0 += BK){
        if constexpr (TRANSA){
            #pragma unroll
            for (int i = tid; i < BK*BM; i += THREADS){
                int kk = i / BM, mm = i % BM;
                int gm = m0+mm, gk = k0+kk;
                float v = 0.f;
                if (gm < M && gk < K) v = A[(long long)gk*lda + gm];
                As[kk][mm] = v;
            }
        } else {
            #pragma unroll
            for (int i = tid; i < BK*BM; i += THREADS){
                int mm = i / BK, kk = i % BK;
                int gm = m0+mm, gk = k0+kk;
                float v = 0.f;
                if (gm < M && gk < K) v = A[(long long)gm*lda + gk];
                As[kk][mm] = v;
            }
        }
        #pragma unroll
        for (int i = tid; i < BK*BN; i += THREADS){
            int kk = i / BN, nn = i % BN;
            int gk = k0+kk, gn = n0+nn;
            float v = 0.f;
            if (gk < K && gn < N) v = B[(long long)gk*ldb + gn];
            Bs[kk][nn] = v;
        }
        __syncthreads();
        #pragma unroll
        for (int kk=0; kk<BK; kk++){
            float ra[TM], rb[TN];
            #pragma unroll
            for (int i=0;i<TM;i+=4)
                *(float4*)&ra[i] = *(const float4*)&As[kk][trow*TM + i];
            #pragma unroll
            for (int j=0;j<TN;j+=4)
                *(float4*)&rb[j] = *(const float4*)&Bs[kk][tcol*TN + j];
            #pragma unroll
            for (int i=0;i<TM;i++)
                #pragma unroll
                for (int j=0;j<TN;j++)
                    acc[i][j] = fmaf(ra[i], rb[j], acc[i][j]);
        }
        __syncthreads();
    }

    #pragma unroll
    for (int i=0;i<TM;i++){
        int r = m0 + trow*TM + i;
        if (r >= M) continue;
        float rowf = (EPI==3) ? rsp[r] : 1.f;
        #pragma unroll
        for (int j=0;j<TN;j++){
            int c = n0 + tcol*TN + j;
            if (c >= N) continue;
            float v = acc[i][j];
            if (EPI==1) v = v + bias[c] + res[(long long)r*ldc + c];
            if (EPI==2){ v = v + bias[c]; v = 0.5f*v*(1.f + erff(v*0.70710678118654752f)); }
            if (EPI==3) v *= rowf;
            C[(long long)r*ldc + c] = v;
        }
    }
}

// ----------------------- global max over kd --------------------------------
__global__ void kmax_reduce(long long total){
    float mx = -1e30f;
    for (long long i = (long long)blockIdx.x*blockDim.x + threadIdx.x; i < total;
         i += (long long)gridDim.x*blockDim.x)
        mx = fmaxf(mx, g_kd[i]);
    mx = wredmax(mx);
    __shared__ float sm[8];
    if ((threadIdx.x&31)==0) sm[threadIdx.x>>5] = mx;
    __syncthreads();
    if (threadIdx.x == 0){
        float m2 = sm[0];
        #pragma unroll
        for (int i=1;i<8;i++) m2 = fmaxf(m2, sm[i]);
        atomicMaxF(&g_kmax, m2);
    }
}

// ---------------------- key features (in place) ----------------------------
__global__ void expk_kernel(const float* __restrict__ kbuf){
    int warp = threadIdx.x>>5, lane = threadIdx.x&31;
    long long row = (long long)blockIdx.x*8 + warp;   // < NB*SEQ
    int batch = (int)(row >> 12);
    int n = (int)(row & 4095);
    int b = batch>>3, hh = batch&7;
    const float* kr = kbuf + ((long long)b*SEQ + n)*DIMV + hh*DHV;
    float a0 = kr[lane], a1 = kr[lane+32];
    float diag = 0.0625f * wredsum(a0*a0 + a1*a1);
    float mx = g_kmax;
    float* dd = g_kd + row*MF;
    #pragma unroll
    for (int i=0;i<9;i++){
        int m = lane + i*32;
        if (m < MF){
            float t = dd[m];
            dd[m] = RATIO * (expf(t - diag - mx) + 1e-4f);
        }
    }
}

// -------------------- query features + d_inv (in place) --------------------
__global__ void expq_kernel(const float* __restrict__ qbuf){
    int warp = threadIdx.x>>5, lane = threadIdx.x&31;
    long long row = (long long)blockIdx.x*8 + warp;
    int batch = (int)(row >> 12);
    int n = (int)(row & 4095);
    int b = batch>>3, hh = batch&7;
    const float* qr = qbuf + ((long long)b*SEQ + n)*DIMV + hh*DHV;
    float a0 = qr[lane], a1 = qr[lane+32];
    float diag = 0.0625f * wredsum(a0*a0 + a1*a1);
    float* dd = g_qd + row*MF;
    float vals[9];
    float mx = -1e30f;
    #pragma unroll
    for (int i=0;i<9;i++){
        int m = lane + i*32;
        if (m < MF){ vals[i] = dd[m]; mx = fmaxf(mx, vals[i]); }
    }
    mx = wredmax(mx);
    const float* kps = g_kpsum + batch*MF;
    float dp = 0.f;
    #pragma unroll
    for (int i=0;i<9;i++){
        int m = lane + i*32;
        if (m < MF){
            float p = RATIO * (expf(vals[i] - diag - mx) + 1e-4f);
            dd[m] = p;
            dp += p * kps[m];
        }
    }
    dp = wredsum(dp);
    if (lane == 0) g_dinv[row] = 1.f / dp;
}

// ------------------------- kp column sums ----------------------------------
__global__ void kpsum_kernel(){
    int m = blockIdx.x*256 + threadIdx.x;
    int batch = blockIdx.y;
    int nchunk = blockIdx.z;
    if (m >= MF) return;
    const float* p = g_kd + (long long)batch*SEQ*MF + (long long)nchunk*512*MF + m;
    float s = 0.f;
    #pragma unroll 4
    for (int n=0; n<512; n++) s += p[(long long)n*MF];
    atomicAdd(&g_kpsum[batch*MF + m], s);
}

// ----------------------------- launch -------------------------------------
extern "C" void kernel_launch(void* const* d_in, const int* in_sizes, int n_in,
                              void* d_out, int out_size){
    const float* x     = (const float*)d_in[0];
    const float* w_q   = (const float*)d_in[1];
    const float* w_k   = (const float*)d_in[2];
    const float* w_v   = (const float*)d_in[3];
    const float* w_o   = (const float*)d_in[4];
    const float* b_o   = (const float*)d_in[5];
    const float* ln1_g = (const float*)d_in[6];
    const float* ln1_b = (const float*)d_in[7];
    const float* ln2_g = (const float*)d_in[8];
    const float* ln2_b = (const float*)d_in[9];
    const float* ff_w1 = (const float*)d_in[10];
    const float* ff_b1 = (const float*)d_in[11];
    const float* ff_w2 = (const float*)d_in[12];
    const float* ff_b2 = (const float*)d_in[13];
    const float* proj  = (const float*)d_in[14];
    float* out = (float*)d_out;

    float *h,*q,*k,*v,*attn,*x1,*ff1,*qd,*kd,*projT,*ctx,*dinv;
    cudaGetSymbolAddress((void**)&h,    g_h);
    cudaGetSymbolAddress((void**)&q,    g_q);
    cudaGetSymbolAddress((void**)&k,    g_k);
    cudaGetSymbolAddress((void**)&v,    g_v);
    cudaGetSymbolAddress((void**)&attn, g_attn);
    cudaGetSymbolAddress((void**)&x1,   g_x1);
    cudaGetSymbolAddress((void**)&ff1,  g_ff1);
    cudaGetSymbolAddress((void**)&qd,   g_qd);
    cudaGetSymbolAddress((void**)&kd,   g_kd);
    cudaGetSymbolAddress((void**)&projT,g_projT);
    cudaGetSymbolAddress((void**)&ctx,  g_ctx);
    cudaGetSymbolAddress((void**)&dinv, g_dinv);

    const long long SQD = (long long)SEQ*DIMV;   // per-b stride in q/k/v/attn
    const long long SQM = (long long)SEQ*MF;     // per-batch stride in qd/kd
    const long long SCX = (long long)MF*DHV;     // per-batch stride in ctx

    // 0. init: projT (with dn), kp_sum = 0, kmax = -inf
    init_kernel<<<(DHV*MF + 255)/256, 256>>>(proj);

    // 1. LN1
    ln_kernel<<<NROWS, 256>>>(x, ln1_g, ln1_b, h);

    // 2. QKV projections
    dim3 gP(DIMV/128, NROWS/128, 1);
    gemm_k<128,128,16,8,8,0,false><<<gP,256>>>(h, w_q, q, NROWS,DIMV,DIMV, DIMV,DIMV,DIMV,
        0,0,0,0,0,0, nullptr,nullptr,nullptr,0,0);
    gemm_k<128,128,16,8,8,0,false><<<gP,256>>>(h, w_k, k, NROWS,DIMV,DIMV, DIMV,DIMV,DIMV,
        0,0,0,0,0,0, nullptr,nullptr,nullptr,0,0);
    gemm_k<128,128,16,8,8,0,false><<<gP,256>>>(h, w_v, v, NROWS,DIMV,DIMV, DIMV,DIMV,DIMV,
        0,0,0,0,0,0, nullptr,nullptr,nullptr,0,0);

    // 3. kd = k_head @ projT   (batched over 64 (b,h))
    dim3 gF((MF+127)/128, SEQ/128, NB);
    gemm_k<128,128,16,8,8,0,false><<<gF,256>>>(k, projT, kd, SEQ,MF,DHV, DIMV,MF,MF,
        SQD, DHV, 0,0, 8*SQM, SQM, nullptr,nullptr,nullptr,0,0);

    // 4. global max over kd
    kmax_reduce<<<2048,256>>>((long long)NB*SEQ*MF);

    // 5. kp = ratio*(exp(kd - diag - kmax) + eps)   (in place)
    expk_kernel<<<(NB*SEQ)/8, 256>>>(k);

    // 6. kp_sum
    kpsum_kernel<<<dim3(2, NB, 8), 256>>>();

    // 7. ctx = kp^T @ v_head   (batched, TRANSA)
    gemm_k<64,64,8,4,4,0,true><<<dim3(1,(MF+63)/64,NB),256>>>(kd, v, ctx, MF,DHV,SEQ, MF,DIMV,DHV,
        8*SQM, SQM, SQD, DHV, 8*SCX, SCX, nullptr,nullptr,nullptr,0,0);

    // 8. qd = q_head @ projT
    gemm_k<128,128,16,8,8,0,false><<<gF,256>>>(q, projT, qd, SEQ,MF,DHV, DIMV,MF,MF,
        SQD, DHV, 0,0, 8*SQM, SQM, nullptr,nullptr,nullptr,0,0);

    // 9. qp (in place) + d_inv
    expq_kernel<<<(NB*SEQ)/8, 256>>>(q);

    // 10. attn = (qp @ ctx) * d_inv  → head-concatenated layout
    gemm_k<64,64,8,4,4,3,false><<<dim3(1,SEQ/64,NB),256>>>(qd, ctx, attn, SEQ,DHV,MF, MF,DHV,DIMV,
        8*SQM, SQM, 8*SCX, SCX, SQD, DHV, nullptr,nullptr, dinv, 8LL*SEQ, SEQ);

    // 11. x1 = x + attn @ w_o + b_o
    gemm_k<128,128,16,8,8,1,false><<<gP,256>>>(attn, w_o, x1, NROWS,DIMV,DIMV, DIMV,DIMV,DIMV,
        0,0,0,0,0,0, b_o, x, nullptr,0,0);

    // 12. LN2 (reuse h)
    ln_kernel<<<NROWS, 256>>>(x1, ln2_g, ln2_b, h);

    // 13. ff1 = gelu(h @ ff_w1 + b1)
    dim3 gFF1(FFD/128, NROWS/128, 1);
    gemm_k<128,128,16,8,8,2,false><<<gFF1,256>>>(h, ff_w1, ff1, NROWS,FFD,DIMV, DIMV,FFD,FFD,
        0,0,0,0,0,0, ff_b1, nullptr, nullptr,0,0);

    // 14. out = x1 + ff1 @ ff_w2 + b2
    gemm_k<128,128,16,8,8,1,false><<<gP,256>>>(ff1, ff_w2, out, NROWS,DIMV,FFD, FFD,DIMV,DIMV,
        0,0,0,0,0,0, ff_b2, x1, nullptr,0,0);
}

// round 4
// speedup vs baseline: 3.1028x; 3.1028x over previous
#include <cuda_runtime.h>
#include <cstdint>
#include <math.h>

#define SEQ   4096
#define BVAL  8
#define DIMV  512
#define HEADS 8
#define DHV   64
#define MF    266
#define MP    288                 /* padded feature dim */
#define NB    (BVAL*HEADS)        /* 64 (b,h) batches */
#define NROWS (BVAL*SEQ)          /* 32768 */
#define FFD   2048
#define QKVD  1536

#define RATIO 0.06131393f         /* 266^-0.5 */
#define DN    0.35355339059327373f

// ----------------------------- scratch ------------------------------------
static __device__ float g_h    [(size_t)NROWS*DIMV];
static __device__ float g_qkv  [(size_t)NROWS*QKVD];
static __device__ float g_attn [(size_t)NROWS*DIMV];
static __device__ float g_x1   [(size_t)NROWS*DIMV];
static __device__ float g_ff1  [(size_t)NROWS*FFD];
static __device__ float g_qd   [(size_t)NB*SEQ*MP];
static __device__ float g_kd   [(size_t)NB*SEQ*MP];
static __device__ float g_projDN[MP*DHV];
static __device__ float g_wqkvT[QKVD*DIMV];
static __device__ float g_woT  [DIMV*DIMV];
static __device__ float g_w1T  [FFD*DIMV];
static __device__ float g_w2T  [DIMV*FFD];
static __device__ float g_kpsum[NB*MP];
static __device__ float g_ctx  [NB*DHV*MP];
static __device__ float g_dinv [(size_t)NB*SEQ];
static __device__ float g_kmax;

// ----------------------------- helpers ------------------------------------
__device__ __forceinline__ float wredsum(float v){
    #pragma unroll
    for (int o=16;o;o>>=1) v += __shfl_xor_sync(0xffffffffu, v, o);
    return v;
}
__device__ __forceinline__ float wredmax(float v){
    #pragma unroll
    for (int o=16;o;o>>=1) v = fmaxf(v, __shfl_xor_sync(0xffffffffu, v, o));
    return v;
}
__device__ void atomicMaxF(float* addr, float val){
    int old = __float_as_int(*addr);
    while (__int_as_float(old) < val){
        int prev = atomicCAS((int*)addr, old, __float_as_int(val));
        if (prev == old) break;
        old = prev;
    }
}
__device__ __forceinline__ float to_tf32(float x){
    uint32_t y; asm("cvt.rna.tf32.f32 %0, %1;" : "=r"(y) : "f"(x));
    return __uint_as_float(y);
}
__device__ __forceinline__ uint32_t smem_u32(const void* p){
    return (uint32_t)__cvta_generic_to_shared(p);
}

#define CP_ASYNC16(dst, src) \
    asm volatile("cp.async.cg.shared.global [%0], [%1], 16;" :: "r"(dst), "l"(src))
#define CP_COMMIT() asm volatile("cp.async.commit_group;")
#define CP_WAIT1()  asm volatile("cp.async.wait_group 1;")
#define CP_WAIT0()  asm volatile("cp.async.wait_group 0;")

#define CVT_TF32_R(x) asm("cvt.rna.tf32.f32 %0, %0;" : "+r"(x))

#define MMA_TF32(c, a, b) \
    asm volatile("mma.sync.aligned.m16n8k8.row.col.f32.tf32.tf32.f32 " \
        "{%0,%1,%2,%3},{%4,%5,%6,%7},{%8,%9},{%0,%1,%2,%3};" \
        : "+f"((c)[0]),"+f"((c)[1]),"+f"((c)[2]),"+f"((c)[3]) \
        : "r"((a)[0]),"r"((a)[1]),"r"((a)[2]),"r"((a)[3]), \
          "r"((b)[0]),"r"((b)[1]))

// ---------------------------- init / transpose -----------------------------
__global__ void init_kernel(const float* __restrict__ proj){
    int t = blockIdx.x*256 + threadIdx.x;
    if (t == 0) g_kmax = -1e30f;
    if (t < MP*DHV){
        int m = t / DHV, d = t % DHV;
        g_projDN[t] = (m < MF) ? proj[m*DHV + d] * DN : 0.f;
    }
    if (t < NB*MP) g_kpsum[t] = 0.f;
}

__global__ void transpose_k(const float* __restrict__ in, float* __restrict__ out, int K, int N){
    __shared__ float t[32][33];
    int k0 = blockIdx.y*32, n0 = blockIdx.x*32;
    int tx = threadIdx.x & 31, ty = threadIdx.x >> 5;
    #pragma unroll
    for (int i=0;i<32;i+=8) t[ty+i][tx] = in[(long long)(k0+ty+i)*N + n0+tx];
    __syncthreads();
    #pragma unroll
    for (int i=0;i<32;i+=8) out[(long long)(n0+ty+i)*K + k0+tx] = t[tx][ty+i];
}

// ----------------------------- layernorm ----------------------------------
__global__ void ln_kernel(const float* __restrict__ x, const float* __restrict__ g,
                          const float* __restrict__ b, float* __restrict__ out){
    __shared__ float red[8];
    long long row = blockIdx.x;
    const float* xr = x + row*DIMV;
    int t = threadIdx.x;
    float v0 = xr[t], v1 = xr[t+256];
    float s = wredsum(v0+v1);
    if ((t&31)==0) red[t>>5] = s;
    __syncthreads();
    float mu = 0.f;
    #pragma unroll
    for (int i=0;i<8;i++) mu += red[i];
    mu *= (1.f/DIMV);
    __syncthreads();
    float d0 = v0-mu, d1 = v1-mu;
    float vs = wredsum(d0*d0 + d1*d1);
    if ((t&31)==0) red[t>>5] = vs;
    __syncthreads();
    float var = 0.f;
    #pragma unroll
    for (int i=0;i<8;i++) var += red[i];
    var *= (1.f/DIMV);
    float inv = rsqrtf(var + 1e-5f);
    out[row*DIMV + t]       = d0*inv*g[t]     + b[t];
    out[row*DIMV + t + 256] = d1*inv*g[t+256] + b[t+256];
}

// ------------------------- tf32 mma.sync GEMM ------------------------------
// D[M,N] = A(MxK) * B(NxK)^T ; fp32 in/out, tf32 multiply, fp32 accumulate.
// TRA: A stored [K][M] (m contiguous). TRB: B stored [K][N] (n contiguous).
// EPI: 0 none, 1 bias+res, 2 bias+exact GELU, 3 per-row scale.
// Batched via blockIdx.z with (z>>3, z&7) stride decomposition.
template<int BM,int BN,int WA_M,int WA_N,bool TRA,bool TRB,int EPI>
__global__ void __launch_bounds__(256) mma_gemm(
    const float* __restrict__ A, const float* __restrict__ B, float* __restrict__ C,
    int M, int Kdim, int lda, int ldb, int ldc,
    long long sAo, long long sAi, long long sBo, long long sBi,
    long long sCo, long long sCi,
    const float* __restrict__ bias, const float* __restrict__ res,
    const float* __restrict__ rs, long long sRo, long long sRi)
{
    constexpr int BK = 32, LDSW = 36;
    constexpr int WM = BM/WA_M, WN = BN/WA_N;
    constexpr int MFR = WM/16, NFR = WN/8;
    constexpr bool ASYNC = !(TRA || TRB);

    extern __shared__ float sm[];
    float* As = sm;                  // [2][BM][LDSW]
    float* Bs = sm + 2*BM*LDSW;      // [2][BN][LDSW]

    int tid = threadIdx.x, lane = tid & 31, wid = tid >> 5;
    int wm = wid % WA_M, wn = wid / WA_M;
    int z = blockIdx.z, zo = z >> 3, zi = z & 7;
    A += (long long)zo*sAo + (long long)zi*sAi;
    B += (long long)zo*sBo + (long long)zi*sBi;
    C += (long long)zo*sCo + (long long)zi*sCi;
    const float* rsb = (EPI==3) ? (rs + (long long)zo*sRo + (long long)zi*sRi) : nullptr;

    int m0 = blockIdx.y * BM;
    int n0 = blockIdx.x * BN;

    float acc[MFR][NFR][4];
    #pragma unroll
    for (int i=0;i<MFR;i++)
        #pragma unroll
        for (int j=0;j<NFR;j++)
            #pragma unroll
            for (int q=0;q<4;q++) acc[i][j][q] = 0.f;

    int S = Kdim / BK;
    int tr = lane >> 2, tc = lane & 3;

    // ---------------- compute on one buffer ----------------
    auto compute = [&](int buf){
        #pragma unroll
        for (int kk=0; kk<4; kk++){
            uint32_t af[MFR][4], bf[NFR][2];
            #pragma unroll
            for (int mi=0; mi<MFR; mi++){
                const float* ap = &As[(buf*BM + wm*WM + mi*16 + tr)*LDSW + kk*8 + tc];
                af[mi][0] = __float_as_uint(ap[0]);
                af[mi][1] = __float_as_uint(ap[8*LDSW]);
                af[mi][2] = __float_as_uint(ap[4]);
                af[mi][3] = __float_as_uint(ap[8*LDSW + 4]);
            }
            #pragma unroll
            for (int ni=0; ni<NFR; ni++){
                const float* bp = &Bs[(buf*BN + wn*WN + ni*8 + tr)*LDSW + kk*8 + tc];
                bf[ni][0] = __float_as_uint(bp[0]);
                bf[ni][1] = __float_as_uint(bp[4]);
            }
            if constexpr (ASYNC){
                #pragma unroll
                for (int mi=0; mi<MFR; mi++){
                    CVT_TF32_R(af[mi][0]); CVT_TF32_R(af[mi][1]);
                    CVT_TF32_R(af[mi][2]); CVT_TF32_R(af[mi][3]);
                }
                #pragma unroll
                for (int ni=0; ni<NFR; ni++){
                    CVT_TF32_R(bf[ni][0]); CVT_TF32_R(bf[ni][1]);
                }
            }
            #pragma unroll
            for (int mi=0; mi<MFR; mi++)
                #pragma unroll
                for (int ni=0; ni<NFR; ni++)
                    MMA_TF32(acc[mi][ni], af[mi], bf[ni]);
        }
    };

    if constexpr (ASYNC){
        // ---------------- cp.async double-buffered loop ----------------
        auto load_async = [&](int buf, int s){
            int k0 = s*BK;
            #pragma unroll
            for (int i=0;i<BM/32;i++){
                int idx = tid + i*256;
                int row = idx >> 3, c4 = idx & 7;
                uint32_t dst = smem_u32(&As[(buf*BM + row)*LDSW + c4*4]);
                CP_ASYNC16(dst, A + (long long)(m0+row)*lda + k0 + c4*4);
            }
            #pragma unroll
            for (int i=0;i<BN/32;i++){
                int idx = tid + i*256;
                int row = idx >> 3, c4 = idx & 7;
                uint32_t dst = smem_u32(&Bs[(buf*BN + row)*LDSW + c4*4]);
                CP_ASYNC16(dst, B + (long long)(n0+row)*ldb + k0 + c4*4);
            }
        };
        load_async(0, 0); CP_COMMIT();
        for (int s=0; s<S; s++){
            if (s+1 < S){ load_async((s+1)&1, s+1); CP_COMMIT(); CP_WAIT1(); }
            else        { CP_WAIT0(); }
            __syncthreads();
            compute(s&1);
            __syncthreads();
        }
    } else {
        // ---------------- synchronous transposed loop ----------------
        for (int s=0; s<S; s++){
            int k0 = s*BK;
            if constexpr (TRA){
                #pragma unroll
                for (int i=0;i<BM/32;i++){
                    int idx = tid + i*256;
                    int kk = idx / (BM/4), m4 = (idx % (BM/4)) * 4;
                    float4 v = *(const float4*)(A + (long long)(k0+kk)*lda + m0 + m4);
                    As[(m4+0)*LDSW + kk] = to_tf32(v.x);
                    As[(m4+1)*LDSW + kk] = to_tf32(v.y);
                    As[(m4+2)*LDSW + kk] = to_tf32(v.z);
                    As[(m4+3)*LDSW + kk] = to_tf32(v.w);
                }
            } else {
                #pragma unroll
                for (int i=0;i<BM/32;i++){
                    int idx = tid + i*256;
                    int row = idx >> 3, c4 = idx & 7;
                    float4 v = *(const float4*)(A + (long long)(m0+row)*lda + k0 + c4*4);
                    v.x=to_tf32(v.x); v.y=to_tf32(v.y); v.z=to_tf32(v.z); v.w=to_tf32(v.w);
                    *(float4*)&As[row*LDSW + c4*4] = v;
                }
            }
            if constexpr (TRB){
                #pragma unroll
                for (int i=0;i<BN/32;i++){
                    int idx = tid + i*256;
                    int kk = idx / (BN/4), n4 = (idx % (BN/4)) * 4;
                    float4 v = *(const float4*)(B + (long long)(k0+kk)*ldb + n0 + n4);
                    Bs[(n4+0)*LDSW + kk] = to_tf32(v.x);
                    Bs[(n4+1)*LDSW + kk] = to_tf32(v.y);
                    Bs[(n4+2)*LDSW + kk] = to_tf32(v.z);
                    Bs[(n4+3)*LDSW + kk] = to_tf32(v.w);
                }
            } else {
                #pragma unroll
                for (int i=0;i<BN/32;i++){
                    int idx = tid + i*256;
                    int row = idx >> 3, c4 = idx & 7;
                    float4 v = *(const float4*)(B + (long long)(n0+row)*ldb + k0 + c4*4);
                    v.x=to_tf32(v.x); v.y=to_tf32(v.y); v.z=to_tf32(v.z); v.w=to_tf32(v.w);
                    *(float4*)&Bs[row*LDSW + c4*4] = v;
                }
            }
            __syncthreads();
            compute(0);
            __syncthreads();
        }
    }

    // ---------------- epilogue ----------------
    #pragma unroll
    for (int mi=0; mi<MFR; mi++){
        #pragma unroll
        for (int ni=0; ni<NFR; ni++){
            int r0 = m0 + wm*WM + mi*16 + tr;
            int c0 = n0 + wn*WN + ni*8 + 2*tc;
            #pragma unroll
            for (int half=0; half<2; half++){
                int r = r0 + half*8;
                float v0 = acc[mi][ni][half*2+0];
                float v1 = acc[mi][ni][half*2+1];
                if (EPI==1){
                    const float* rr = res + (long long)r*ldc + c0;
                    v0 += bias[c0]   + rr[0];
                    v1 += bias[c0+1] + rr[1];
                }
                if (EPI==2){
                    v0 += bias[c0];   v0 = 0.5f*v0*(1.f + erff(v0*0.70710678118654752f));
                    v1 += bias[c0+1]; v1 = 0.5f*v1*(1.f + erff(v1*0.70710678118654752f));
                }
                if (EPI==3){
                    float sc = rsb[r];
                    v0 *= sc; v1 *= sc;
                }
                *(float2*)(C + (long long)r*ldc + c0) = make_float2(v0, v1);
            }
        }
    }
}

// ----------------------- kd global max (cols < 266) ------------------------
__global__ void kmax_kernel(){
    __shared__ float sm[8];
    int warp = threadIdx.x>>5, lane = threadIdx.x&31;
    long long row = (long long)blockIdx.x*8 + warp;
    const float* dd = g_kd + row*MP;
    float mx = -1e30f;
    #pragma unroll
    for (int i=0;i<9;i++){
        int m = lane + i*32;
        if (m < MF) mx = fmaxf(mx, dd[m]);
    }
    mx = wredmax(mx);
    if (lane==0) sm[warp] = mx;
    __syncthreads();
    if (threadIdx.x == 0){
        float m2 = sm[0];
        #pragma unroll
        for (int i=1;i<8;i++) m2 = fmaxf(m2, sm[i]);
        atomicMaxF(&g_kmax, m2);
    }
}

// ---------------------- key features (in place, pad->0) --------------------
__global__ void expk_kernel(){
    int warp = threadIdx.x>>5, lane = threadIdx.x&31;
    long long row = (long long)blockIdx.x*8 + warp;
    int batch = (int)(row >> 12);
    int n = (int)(row & 4095);
    int b = batch>>3, hh = batch&7;
    const float* kr = g_qkv + ((long long)b*SEQ + n)*QKVD + DIMV + hh*DHV;
    float a0 = kr[lane], a1 = kr[lane+32];
    float diag = 0.0625f * wredsum(a0*a0 + a1*a1);
    float mx = g_kmax;
    float* dd = g_kd + row*MP;
    #pragma unroll
    for (int i=0;i<9;i++){
        int m = lane + i*32;
        float o = 0.f;
        if (m < MF) o = RATIO * (expf(dd[m] - diag - mx) + 1e-4f);
        dd[m] = o;
    }
}

// ------------------ query features + d_inv (in place, pad->0) --------------
__global__ void expq_kernel(){
    int warp = threadIdx.x>>5, lane = threadIdx.x&31;
    long long row = (long long)blockIdx.x*8 + warp;
    int batch = (int)(row >> 12);
    int n = (int)(row & 4095);
    int b = batch>>3, hh = batch&7;
    const float* qr = g_qkv + ((long long)b*SEQ + n)*QKVD + hh*DHV;
    float a0 = qr[lane], a1 = qr[lane+32];
    float diag = 0.0625f * wredsum(a0*a0 + a1*a1);
    float* dd = g_qd + row*MP;
    float vals[9];
    float mx = -1e30f;
    #pragma unroll
    for (int i=0;i<9;i++){
        int m = lane + i*32;
        vals[i] = dd[m];
        if (m < MF) mx = fmaxf(mx, vals[i]);
    }
    mx = wredmax(mx);
    const float* kps = g_kpsum + batch*MP;
    float dp = 0.f;
    #pragma unroll
    for (int i=0;i<9;i++){
        int m = lane + i*32;
        float p = 0.f;
        if (m < MF){
            p = RATIO * (expf(vals[i] - diag - mx) + 1e-4f);
            dp += p * kps[m];
        }
        dd[m] = p;
    }
    dp = wredsum(dp);
    if (lane == 0) g_dinv[row] = 1.f / dp;
}

// ------------------------- kp column sums ----------------------------------
__global__ void kpsum_kernel(){
    int m = blockIdx.x*256 + threadIdx.x;
    int batch = blockIdx.y;
    int nchunk = blockIdx.z;
    if (m >= MP) return;
    const float* p = g_kd + (long long)batch*SEQ*MP + (long long)nchunk*512*MP + m;
    float s = 0.f;
    #pragma unroll 4
    for (int n=0; n<512; n++) s += p[(long long)n*MP];
    atomicAdd(&g_kpsum[batch*MP + m], s);
}

// ----------------------------- launch -------------------------------------
extern "C" void kernel_launch(void* const* d_in, const int* in_sizes, int n_in,
                              void* d_out, int out_size){
    const float* x     = (const float*)d_in[0];
    const float* w_q   = (const float*)d_in[1];
    const float* w_k   = (const float*)d_in[2];
    const float* w_v   = (const float*)d_in[3];
    const float* w_o   = (const float*)d_in[4];
    const float* b_o   = (const float*)d_in[5];
    const float* ln1_g = (const float*)d_in[6];
    const float* ln1_b = (const float*)d_in[7];
    const float* ln2_g = (const float*)d_in[8];
    const float* ln2_b = (const float*)d_in[9];
    const float* ff_w1 = (const float*)d_in[10];
    const float* ff_b1 = (const float*)d_in[11];
    const float* ff_w2 = (const float*)d_in[12];
    const float* ff_b2 = (const float*)d_in[13];
    const float* proj  = (const float*)d_in[14];
    float* out = (float*)d_out;

    float *h,*qkv,*attn,*x1,*ff1,*qd,*kd,*projDN,*wqkvT,*woT,*w1T,*w2T,*ctx,*dinv;
    cudaGetSymbolAddress((void**)&h,     g_h);
    cudaGetSymbolAddress((void**)&qkv,   g_qkv);
    cudaGetSymbolAddress((void**)&attn,  g_attn);
    cudaGetSymbolAddress((void**)&x1,    g_x1);
    cudaGetSymbolAddress((void**)&ff1,   g_ff1);
    cudaGetSymbolAddress((void**)&qd,    g_qd);
    cudaGetSymbolAddress((void**)&kd,    g_kd);
    cudaGetSymbolAddress((void**)&projDN,g_projDN);
    cudaGetSymbolAddress((void**)&wqkvT, g_wqkvT);
    cudaGetSymbolAddress((void**)&woT,   g_woT);
    cudaGetSymbolAddress((void**)&w1T,   g_w1T);
    cudaGetSymbolAddress((void**)&w2T,   g_w2T);
    cudaGetSymbolAddress((void**)&ctx,   g_ctx);
    cudaGetSymbolAddress((void**)&dinv,  g_dinv);

    const long long SQM = (long long)SEQ*MP;
    const long long SCX = (long long)DHV*MP;
    const long long SAB = (long long)SEQ*QKVD;

    // dynamic smem: (2*BM + 2*BN) * 36 floats
    const int SM_128_128 = (2*128 + 2*128)*36*4;  // 73728
    const int SM_128_96  = (2*128 + 2*96 )*36*4;  // 64512
    const int SM_64_96   = (2*64  + 2*96 )*36*4;  // 46080
    const int SM_128_64  = (2*128 + 2*64 )*36*4;  // 55296
    cudaFuncSetAttribute((const void*)mma_gemm<128,128,2,4,false,false,0>, cudaFuncAttributeMaxDynamicSharedMemorySize, SM_128_128);
    cudaFuncSetAttribute((const void*)mma_gemm<128,128,2,4,false,false,1>, cudaFuncAttributeMaxDynamicSharedMemorySize, SM_128_128);
    cudaFuncSetAttribute((const void*)mma_gemm<128,128,2,4,false,false,2>, cudaFuncAttributeMaxDynamicSharedMemorySize, SM_128_128);
    cudaFuncSetAttribute((const void*)mma_gemm<128,96,2,4,false,false,0>,  cudaFuncAttributeMaxDynamicSharedMemorySize, SM_128_96);
    cudaFuncSetAttribute((const void*)mma_gemm<64,96,4,2,true,true,0>,     cudaFuncAttributeMaxDynamicSharedMemorySize, SM_64_96);
    cudaFuncSetAttribute((const void*)mma_gemm<128,64,2,4,false,false,3>,  cudaFuncAttributeMaxDynamicSharedMemorySize, SM_128_64);

    // 0. weight transposes + init
    transpose_k<<<dim3(16,16),256>>>(w_q, wqkvT,            DIMV, DIMV);
    transpose_k<<<dim3(16,16),256>>>(w_k, wqkvT + 512*512,  DIMV, DIMV);
    transpose_k<<<dim3(16,16),256>>>(w_v, wqkvT + 1024*512, DIMV, DIMV);
    transpose_k<<<dim3(16,16),256>>>(w_o, woT,              DIMV, DIMV);
    transpose_k<<<dim3(64,16),256>>>(ff_w1, w1T,            DIMV, FFD);
    transpose_k<<<dim3(16,64),256>>>(ff_w2, w2T,            FFD, DIMV);
    init_kernel<<<72,256>>>(proj);

    // 1. LN1
    ln_kernel<<<NROWS, 256>>>(x, ln1_g, ln1_b, h);

    // 2. fused QKV
    mma_gemm<128,128,2,4,false,false,0><<<dim3(QKVD/128, NROWS/128, 1), 256, SM_128_128>>>(
        h, wqkvT, qkv, NROWS, DIMV, DIMV, DIMV, QKVD,
        0,0,0,0,0,0, nullptr,nullptr,nullptr,0,0);

    // 3. kd = k_head @ projDN^T
    mma_gemm<128,96,2,4,false,false,0><<<dim3(MP/96, SEQ/128, NB), 256, SM_128_96>>>(
        qkv + DIMV, projDN, kd, SEQ, DHV, QKVD, DHV, MP,
        SAB, DHV, 0,0, 8*SQM, SQM, nullptr,nullptr,nullptr,0,0);

    // 4. global max over kd
    kmax_kernel<<<(NB*SEQ)/8, 256>>>();

    // 5. kp in place
    expk_kernel<<<(NB*SEQ)/8, 256>>>();

    // 6. kp column sums
    kpsum_kernel<<<dim3(2, NB, 8), 256>>>();

    // 7. ctx = v^T @ kp  (TRA, TRB)
    mma_gemm<64,96,4,2,true,true,0><<<dim3(MP/96, 1, NB), 256, SM_64_96>>>(
        qkv + 2*DIMV, kd, ctx, DHV, SEQ, QKVD, MP, MP,
        SAB, DHV, 8*SQM, SQM, 8*SCX, SCX, nullptr,nullptr,nullptr,0,0);

    // 8. qd = q_head @ projDN^T
    mma_gemm<128,96,2,4,false,false,0><<<dim3(MP/96, SEQ/128, NB), 256, SM_128_96>>>(
        qkv, projDN, qd, SEQ, DHV, QKVD, DHV, MP,
        SAB, DHV, 0,0, 8*SQM, SQM, nullptr,nullptr,nullptr,0,0);

    // 9. qp in place + d_inv
    expq_kernel<<<(NB*SEQ)/8, 256>>>();

    // 10. attn = (qp @ ctx^T) * d_inv
    mma_gemm<128,64,2,4,false,false,3><<<dim3(1, SEQ/128, NB), 256, SM_128_64>>>(
        qd, ctx, attn, SEQ, MP, MP, MP, DIMV,
        8*SQM, SQM, 8*SCX, SCX, (long long)SEQ*DIMV, DHV,
        nullptr, nullptr, dinv, 8LL*SEQ, SEQ);

    // 11. x1 = x + attn @ w_o + b_o
    mma_gemm<128,128,2,4,false,false,1><<<dim3(DIMV/128, NROWS/128, 1), 256, SM_128_128>>>(
        attn, woT, x1, NROWS, DIMV, DIMV, DIMV, DIMV,
        0,0,0,0,0,0, b_o, x, nullptr,0,0);

    // 12. LN2
    ln_kernel<<<NROWS, 256>>>(x1, ln2_g, ln2_b, h);

    // 13. ff1 = gelu(h @ W1 + b1)
    mma_gemm<128,128,2,4,false,false,2><<<dim3(FFD/128, NROWS/128, 1), 256, SM_128_128>>>(
        h, w1T, ff1, NROWS, DIMV, DIMV, DIMV, FFD,
        0,0,0,0,0,0, ff_b1, nullptr, nullptr,0,0);

    // 14. out = x1 + ff1 @ W2 + b2
    mma_gemm<128,128,2,4,false,false,1><<<dim3(DIMV/128, NROWS/128, 1), 256, SM_128_128>>>(
        ff1, w2T, out, NROWS, FFD, FFD, FFD, DIMV,
        0,0,0,0,0,0, ff_b2, x1, nullptr,0,0);
}

// round 5
// speedup vs baseline: 3.7952x; 1.2232x over previous
#include <cuda_runtime.h>
#include <cstdint>
#include <math.h>

#define SEQ   4096
#define BVAL  8
#define DIMV  512
#define HEADS 8
#define DHV   64
#define MF    266
#define MP    288                 /* padded feature dim */
#define NB    (BVAL*HEADS)        /* 64 (b,h) batches */
#define NROWS (BVAL*SEQ)          /* 32768 */
#define FFD   2048
#define QKVD  1536

#define RATIO 0.06131393f         /* 266^-0.5 */
#define DN    0.35355339059327373f

// ----------------------------- scratch ------------------------------------
static __device__ float g_h    [(size_t)NROWS*DIMV];
static __device__ float g_qkv  [(size_t)NROWS*QKVD];
static __device__ float g_attn [(size_t)NROWS*DIMV];
static __device__ float g_x1   [(size_t)NROWS*DIMV];
static __device__ float g_ff1  [(size_t)NROWS*FFD];
static __device__ float g_qd   [(size_t)NB*SEQ*MP];
static __device__ float g_kd   [(size_t)NB*SEQ*MP];
static __device__ float g_projDN[MP*DHV];
static __device__ float g_wqkvT[QKVD*DIMV];
static __device__ float g_woT  [DIMV*DIMV];
static __device__ float g_w1T  [FFD*DIMV];
static __device__ float g_w2T  [DIMV*FFD];
static __device__ float g_kpsum[NB*MP];
static __device__ float g_ctx  [NB*DHV*MP];
static __device__ float g_dinv [(size_t)NB*SEQ];
static __device__ float g_kmax;

// ----------------------------- helpers ------------------------------------
__device__ __forceinline__ float wredsum(float v){
    #pragma unroll
    for (int o=16;o;o>>=1) v += __shfl_xor_sync(0xffffffffu, v, o);
    return v;
}
__device__ __forceinline__ float wredmax(float v){
    #pragma unroll
    for (int o=16;o;o>>=1) v = fmaxf(v, __shfl_xor_sync(0xffffffffu, v, o));
    return v;
}
__device__ void atomicMaxF(float* addr, float val){
    int old = __float_as_int(*addr);
    while (__int_as_float(old) < val){
        int prev = atomicCAS((int*)addr, old, __float_as_int(val));
        if (prev == old) break;
        old = prev;
    }
}
__device__ __forceinline__ float to_tf32(float x){
    uint32_t y; asm("cvt.rna.tf32.f32 %0, %1;" : "=r"(y) : "f"(x));
    return __uint_as_float(y);
}
__device__ __forceinline__ uint32_t smem_u32(const void* p){
    return (uint32_t)__cvta_generic_to_shared(p);
}

#define CP_ASYNC16(dst, src) \
    asm volatile("cp.async.cg.shared.global [%0], [%1], 16;" :: "r"(dst), "l"(src))
#define CP_COMMIT() asm volatile("cp.async.commit_group;")
#define CP_WAIT1()  asm volatile("cp.async.wait_group 1;")
#define CP_WAIT0()  asm volatile("cp.async.wait_group 0;")

#define CVT_TF32_R(x) asm("cvt.rna.tf32.f32 %0, %0;" : "+r"(x))

#define MMA_TF32(c, a, b) \
    asm volatile("mma.sync.aligned.m16n8k8.row.col.f32.tf32.tf32.f32 " \
        "{%0,%1,%2,%3},{%4,%5,%6,%7},{%8,%9},{%0,%1,%2,%3};" \
        : "+f"((c)[0]),"+f"((c)[1]),"+f"((c)[2]),"+f"((c)[3]) \
        : "r"((a)[0]),"r"((a)[1]),"r"((a)[2]),"r"((a)[3]), \
          "r"((b)[0]),"r"((b)[1]))

// ---------------------------- init / transpose -----------------------------
__global__ void init_kernel(const float* __restrict__ proj){
    int t = blockIdx.x*256 + threadIdx.x;
    if (t == 0) g_kmax = -1e30f;
    if (t < MP*DHV){
        int m = t / DHV, d = t % DHV;
        g_projDN[t] = (m < MF) ? proj[m*DHV + d] * DN : 0.f;
    }
    if (t < NB*MP) g_kpsum[t] = 0.f;
}

__global__ void transpose_k(const float* __restrict__ in, float* __restrict__ out, int K, int N){
    __shared__ float t[32][33];
    int k0 = blockIdx.y*32, n0 = blockIdx.x*32;
    int tx = threadIdx.x & 31, ty = threadIdx.x >> 5;
    #pragma unroll
    for (int i=0;i<32;i+=8) t[ty+i][tx] = in[(long long)(k0+ty+i)*N + n0+tx];
    __syncthreads();
    #pragma unroll
    for (int i=0;i<32;i+=8) out[(long long)(n0+ty+i)*K + k0+tx] = t[tx][ty+i];
}

// ----------------------------- layernorm ----------------------------------
__global__ void ln_kernel(const float* __restrict__ x, const float* __restrict__ g,
                          const float* __restrict__ b, float* __restrict__ out){
    __shared__ float red[8];
    long long row = blockIdx.x;
    const float* xr = x + row*DIMV;
    int t = threadIdx.x;
    float v0 = xr[t], v1 = xr[t+256];
    float s = wredsum(v0+v1);
    if ((t&31)==0) red[t>>5] = s;
    __syncthreads();
    float mu = 0.f;
    #pragma unroll
    for (int i=0;i<8;i++) mu += red[i];
    mu *= (1.f/DIMV);
    __syncthreads();
    float d0 = v0-mu, d1 = v1-mu;
    float vs = wredsum(d0*d0 + d1*d1);
    if ((t&31)==0) red[t>>5] = vs;
    __syncthreads();
    float var = 0.f;
    #pragma unroll
    for (int i=0;i<8;i++) var += red[i];
    var *= (1.f/DIMV);
    float inv = rsqrtf(var + 1e-5f);
    out[row*DIMV + t]       = d0*inv*g[t]     + b[t];
    out[row*DIMV + t + 256] = d1*inv*g[t+256] + b[t+256];
}

// ------------------------- tf32 mma.sync GEMM ------------------------------
// D[M,N] = A(MxK) * B(NxK)^T ; fp32 in/out, tf32 multiply, fp32 accumulate.
// EPI: 0 none, 1 bias+res, 2 bias+exact GELU, 3 per-row scale,
//      4 store + fused global max over cols<MF (into g_kmax).
// Batched via blockIdx.z with (z>>3, z&7) stride decomposition.
template<int BM,int BN,int WA_M,int WA_N,int EPI>
__global__ void __launch_bounds__(256,2) mma_gemm(
    const float* __restrict__ A, const float* __restrict__ B, float* __restrict__ C,
    int M, int Kdim, int lda, int ldb, int ldc,
    long long sAo, long long sAi, long long sBo, long long sBi,
    long long sCo, long long sCi,
    const float* __restrict__ bias, const float* __restrict__ res,
    const float* __restrict__ rs, long long sRo, long long sRi)
{
    constexpr int BK = 32, LDSW = 36;
    constexpr int WM = BM/WA_M, WN = BN/WA_N;
    constexpr int MFR = WM/16, NFR = WN/8;

    extern __shared__ float sm[];
    float* As = sm;                  // [2][BM][LDSW]
    float* Bs = sm + 2*BM*LDSW;      // [2][BN][LDSW]
    __shared__ float s_red[8];

    int tid = threadIdx.x, lane = tid & 31, wid = tid >> 5;
    int wm = wid % WA_M, wn = wid / WA_M;
    int z = blockIdx.z, zo = z >> 3, zi = z & 7;
    A += (long long)zo*sAo + (long long)zi*sAi;
    B += (long long)zo*sBo + (long long)zi*sBi;
    C += (long long)zo*sCo + (long long)zi*sCi;
    const float* rsb = (EPI==3) ? (rs + (long long)zo*sRo + (long long)zi*sRi) : nullptr;

    int m0 = blockIdx.y * BM;
    int n0 = blockIdx.x * BN;

    float acc[MFR][NFR][4];
    #pragma unroll
    for (int i=0;i<MFR;i++)
        #pragma unroll
        for (int j=0;j<NFR;j++)
            #pragma unroll
            for (int q=0;q<4;q++) acc[i][j][q] = 0.f;

    int S = Kdim / BK;
    int tr = lane >> 2, tc = lane & 3;

    auto compute = [&](int buf){
        #pragma unroll
        for (int kk=0; kk<4; kk++){
            uint32_t af[MFR][4], bf[NFR][2];
            #pragma unroll
            for (int mi=0; mi<MFR; mi++){
                const float* ap = &As[(buf*BM + wm*WM + mi*16 + tr)*LDSW + kk*8 + tc];
                af[mi][0] = __float_as_uint(ap[0]);
                af[mi][1] = __float_as_uint(ap[8*LDSW]);
                af[mi][2] = __float_as_uint(ap[4]);
                af[mi][3] = __float_as_uint(ap[8*LDSW + 4]);
            }
            #pragma unroll
            for (int ni=0; ni<NFR; ni++){
                const float* bp = &Bs[(buf*BN + wn*WN + ni*8 + tr)*LDSW + kk*8 + tc];
                bf[ni][0] = __float_as_uint(bp[0]);
                bf[ni][1] = __float_as_uint(bp[4]);
            }
            #pragma unroll
            for (int mi=0; mi<MFR; mi++){
                CVT_TF32_R(af[mi][0]); CVT_TF32_R(af[mi][1]);
                CVT_TF32_R(af[mi][2]); CVT_TF32_R(af[mi][3]);
            }
            #pragma unroll
            for (int ni=0; ni<NFR; ni++){
                CVT_TF32_R(bf[ni][0]); CVT_TF32_R(bf[ni][1]);
            }
            #pragma unroll
            for (int mi=0; mi<MFR; mi++)
                #pragma unroll
                for (int ni=0; ni<NFR; ni++)
                    MMA_TF32(acc[mi][ni], af[mi], bf[ni]);
        }
    };

    auto load_async = [&](int buf, int s){
        int k0 = s*BK;
        #pragma unroll
        for (int i=0;i<BM/32;i++){
            int idx = tid + i*256;
            int row = idx >> 3, c4 = idx & 7;
            uint32_t dst = smem_u32(&As[(buf*BM + row)*LDSW + c4*4]);
            CP_ASYNC16(dst, A + (long long)(m0+row)*lda + k0 + c4*4);
        }
        #pragma unroll
        for (int i=0;i<BN/32;i++){
            int idx = tid + i*256;
            int row = idx >> 3, c4 = idx & 7;
            uint32_t dst = smem_u32(&Bs[(buf*BN + row)*LDSW + c4*4]);
            CP_ASYNC16(dst, B + (long long)(n0+row)*ldb + k0 + c4*4);
        }
    };
    load_async(0, 0); CP_COMMIT();
    for (int s=0; s<S; s++){
        if (s+1 < S){ load_async((s+1)&1, s+1); CP_COMMIT(); CP_WAIT1(); }
        else        { CP_WAIT0(); }
        __syncthreads();
        compute(s&1);
        __syncthreads();
    }

    // ---------------- epilogue ----------------
    float tmax = -1e30f;
    #pragma unroll
    for (int mi=0; mi<MFR; mi++){
        #pragma unroll
        for (int ni=0; ni<NFR; ni++){
            int r0 = m0 + wm*WM + mi*16 + tr;
            int c0 = n0 + wn*WN + ni*8 + 2*tc;
            #pragma unroll
            for (int half=0; half<2; half++){
                int r = r0 + half*8;
                float v0 = acc[mi][ni][half*2+0];
                float v1 = acc[mi][ni][half*2+1];
                if (EPI==1){
                    const float* rr = res + (long long)r*ldc + c0;
                    v0 += bias[c0]   + rr[0];
                    v1 += bias[c0+1] + rr[1];
                }
                if (EPI==2){
                    v0 += bias[c0];   v0 = 0.5f*v0*(1.f + erff(v0*0.70710678118654752f));
                    v1 += bias[c0+1]; v1 = 0.5f*v1*(1.f + erff(v1*0.70710678118654752f));
                }
                if (EPI==3){
                    float sc = rsb[r];
                    v0 *= sc; v1 *= sc;
                }
                if (EPI==4){
                    if (c0   < MF) tmax = fmaxf(tmax, v0);
                    if (c0+1 < MF) tmax = fmaxf(tmax, v1);
                }
                *(float2*)(C + (long long)r*ldc + c0) = make_float2(v0, v1);
            }
        }
    }
    if (EPI==4){
        tmax = wredmax(tmax);
        if (lane==0) s_red[wid] = tmax;
        __syncthreads();
        if (tid==0){
            float m2 = s_red[0];
            #pragma unroll
            for (int i=1;i<8;i++) m2 = fmaxf(m2, s_red[i]);
            atomicMaxF(&g_kmax, m2);
        }
    }
}

// --------------------- ctx GEMM: ctx[64,288] = v^T @ kp --------------------
// A = v section of qkv: [K=4096 rows][64 cols] (row stride QKVD)
// B = kd: [K=4096 rows][288 cols] (row stride MP)
// C = ctx: [64 rows][288 cols] per batch.
// K-major smem tiles, cp.async double-buffered.
__global__ void __launch_bounds__(256) ctx_gemm(
    const float* __restrict__ Abase, const float* __restrict__ Bbase, float* __restrict__ Cbase)
{
    constexpr int BK=32, LDM=72, LDN=104;
    __shared__ float As[2][BK][LDM];
    __shared__ float Bs[2][BK][LDN];

    int tid = threadIdx.x, lane = tid & 31, wid = tid >> 5;
    int wm = wid & 1, wn = wid >> 1;          // 2 x 4 warps ; WM=32, WN=24
    int tr = lane >> 2, tc = lane & 3;
    int z = blockIdx.z, zo = z >> 3, zi = z & 7;
    const float* A = Abase + (long long)zo*SEQ*QKVD + zi*DHV;
    const float* B = Bbase + (long long)z*SEQ*MP;
    float* C = Cbase + (long long)z*DHV*MP;
    int n0 = blockIdx.x * 96;

    float acc[2][3][4];
    #pragma unroll
    for (int i=0;i<2;i++)
        #pragma unroll
        for (int j=0;j<3;j++)
            #pragma unroll
            for (int q=0;q<4;q++) acc[i][j][q] = 0.f;

    auto load_async = [&](int buf, int s){
        int k0 = s*BK;
        #pragma unroll
        for (int i=0;i<2;i++){                 // A: 32x16 float4
            int idx = tid + i*256;
            int r = idx >> 4, c = idx & 15;
            uint32_t dst = smem_u32(&As[buf][r][c*4]);
            CP_ASYNC16(dst, A + (long long)(k0+r)*QKVD + c*4);
        }
        #pragma unroll
        for (int i=0;i<3;i++){                 // B: 32x24 float4
            int idx = tid + i*256;
            int r = idx / 24, c = idx % 24;
            uint32_t dst = smem_u32(&Bs[buf][r][c*4]);
            CP_ASYNC16(dst, B + (long long)(k0+r)*MP + n0 + c*4);
        }
    };

    auto compute = [&](int buf){
        #pragma unroll
        for (int kk=0; kk<4; kk++){
            uint32_t af[2][4], bf[3][2];
            #pragma unroll
            for (int mi=0; mi<2; mi++){
                int m = wm*32 + mi*16 + tr;
                af[mi][0] = __float_as_uint(As[buf][kk*8+tc  ][m]);
                af[mi][1] = __float_as_uint(As[buf][kk*8+tc  ][m+8]);
                af[mi][2] = __float_as_uint(As[buf][kk*8+tc+4][m]);
                af[mi][3] = __float_as_uint(As[buf][kk*8+tc+4][m+8]);
                CVT_TF32_R(af[mi][0]); CVT_TF32_R(af[mi][1]);
                CVT_TF32_R(af[mi][2]); CVT_TF32_R(af[mi][3]);
            }
            #pragma unroll
            for (int ni=0; ni<3; ni++){
                int n = wn*24 + ni*8 + tr;
                bf[ni][0] = __float_as_uint(Bs[buf][kk*8+tc  ][n]);
                bf[ni][1] = __float_as_uint(Bs[buf][kk*8+tc+4][n]);
                CVT_TF32_R(bf[ni][0]); CVT_TF32_R(bf[ni][1]);
            }
            #pragma unroll
            for (int mi=0; mi<2; mi++)
                #pragma unroll
                for (int ni=0; ni<3; ni++)
                    MMA_TF32(acc[mi][ni], af[mi], bf[ni]);
        }
    };

    const int S = SEQ/BK;      // 128
    load_async(0, 0); CP_COMMIT();
    for (int s=0; s<S; s++){
        if (s+1 < S){ load_async((s+1)&1, s+1); CP_COMMIT(); CP_WAIT1(); }
        else        { CP_WAIT0(); }
        __syncthreads();
        compute(s&1);
        __syncthreads();
    }

    #pragma unroll
    for (int mi=0; mi<2; mi++){
        #pragma unroll
        for (int ni=0; ni<3; ni++){
            int r0 = wm*32 + mi*16 + tr;
            int c0 = n0 + wn*24 + ni*8 + 2*tc;
            #pragma unroll
            for (int half=0; half<2; half++){
                int r = r0 + half*8;
                *(float2*)(C + (long long)r*MP + c0) =
                    make_float2(acc[mi][ni][half*2+0], acc[mi][ni][half*2+1]);
            }
        }
    }
}

// ---------------------- key features (in place, pad->0) --------------------
__global__ void expk_kernel(){
    int warp = threadIdx.x>>5, lane = threadIdx.x&31;
    long long row = (long long)blockIdx.x*8 + warp;
    int batch = (int)(row >> 12);
    int n = (int)(row & 4095);
    int b = batch>>3, hh = batch&7;
    const float* kr = g_qkv + ((long long)b*SEQ + n)*QKVD + DIMV + hh*DHV;
    float a0 = kr[lane], a1 = kr[lane+32];
    float diag = 0.0625f * wredsum(a0*a0 + a1*a1);
    float mx = g_kmax;
    float* dd = g_kd + row*MP;
    #pragma unroll
    for (int i=0;i<9;i++){
        int m = lane + i*32;
        float o = 0.f;
        if (m < MF) o = RATIO * (expf(dd[m] - diag - mx) + 1e-4f);
        dd[m] = o;
    }
}

// ------------------ query features + d_inv (in place, pad->0) --------------
__global__ void expq_kernel(){
    int warp = threadIdx.x>>5, lane = threadIdx.x&31;
    long long row = (long long)blockIdx.x*8 + warp;
    int batch = (int)(row >> 12);
    int n = (int)(row & 4095);
    int b = batch>>3, hh = batch&7;
    const float* qr = g_qkv + ((long long)b*SEQ + n)*QKVD + hh*DHV;
    float a0 = qr[lane], a1 = qr[lane+32];
    float diag = 0.0625f * wredsum(a0*a0 + a1*a1);
    float* dd = g_qd + row*MP;
    float vals[9];
    float mx = -1e30f;
    #pragma unroll
    for (int i=0;i<9;i++){
        int m = lane + i*32;
        vals[i] = dd[m];
        if (m < MF) mx = fmaxf(mx, vals[i]);
    }
    mx = wredmax(mx);
    const float* kps = g_kpsum + batch*MP;
    float dp = 0.f;
    #pragma unroll
    for (int i=0;i<9;i++){
        int m = lane + i*32;
        float p = 0.f;
        if (m < MF){
            p = RATIO * (expf(vals[i] - diag - mx) + 1e-4f);
            dp += p * kps[m];
        }
        dd[m] = p;
    }
    dp = wredsum(dp);
    if (lane == 0) g_dinv[row] = 1.f / dp;
}

// ------------------------- kp column sums ----------------------------------
__global__ void kpsum_kernel(){
    int m = blockIdx.x*256 + threadIdx.x;
    int batch = blockIdx.y;
    int nchunk = blockIdx.z;
    if (m >= MP) return;
    const float* p = g_kd + (long long)batch*SEQ*MP + (long long)nchunk*512*MP + m;
    float s = 0.f;
    #pragma unroll 4
    for (int n=0; n<512; n++) s += p[(long long)n*MP];
    atomicAdd(&g_kpsum[batch*MP + m], s);
}

// ----------------------------- launch -------------------------------------
extern "C" void kernel_launch(void* const* d_in, const int* in_sizes, int n_in,
                              void* d_out, int out_size){
    const float* x     = (const float*)d_in[0];
    const float* w_q   = (const float*)d_in[1];
    const float* w_k   = (const float*)d_in[2];
    const float* w_v   = (const float*)d_in[3];
    const float* w_o   = (const float*)d_in[4];
    const float* b_o   = (const float*)d_in[5];
    const float* ln1_g = (const float*)d_in[6];
    const float* ln1_b = (const float*)d_in[7];
    const float* ln2_g = (const float*)d_in[8];
    const float* ln2_b = (const float*)d_in[9];
    const float* ff_w1 = (const float*)d_in[10];
    const float* ff_b1 = (const float*)d_in[11];
    const float* ff_w2 = (const float*)d_in[12];
    const float* ff_b2 = (const float*)d_in[13];
    const float* proj  = (const float*)d_in[14];
    float* out = (float*)d_out;

    float *h,*qkv,*attn,*x1,*ff1,*qd,*kd,*projDN,*wqkvT,*woT,*w1T,*w2T,*ctx,*dinv;
    cudaGetSymbolAddress((void**)&h,     g_h);
    cudaGetSymbolAddress((void**)&qkv,   g_qkv);
    cudaGetSymbolAddress((void**)&attn,  g_attn);
    cudaGetSymbolAddress((void**)&x1,    g_x1);
    cudaGetSymbolAddress((void**)&ff1,   g_ff1);
    cudaGetSymbolAddress((void**)&qd,    g_qd);
    cudaGetSymbolAddress((void**)&kd,    g_kd);
    cudaGetSymbolAddress((void**)&projDN,g_projDN);
    cudaGetSymbolAddress((void**)&wqkvT, g_wqkvT);
    cudaGetSymbolAddress((void**)&woT,   g_woT);
    cudaGetSymbolAddress((void**)&w1T,   g_w1T);
    cudaGetSymbolAddress((void**)&w2T,   g_w2T);
    cudaGetSymbolAddress((void**)&ctx,   g_ctx);
    cudaGetSymbolAddress((void**)&dinv,  g_dinv);

    const long long SQM = (long long)SEQ*MP;
    const long long SCX = (long long)DHV*MP;
    const long long SAB = (long long)SEQ*QKVD;

    const int SM_128_128 = (2*128 + 2*128)*36*4;  // 73728
    const int SM_128_96  = (2*128 + 2*96 )*36*4;  // 64512
    const int SM_128_64  = (2*128 + 2*64 )*36*4;  // 55296
    cudaFuncSetAttribute((const void*)mma_gemm<128,128,2,4,0>, cudaFuncAttributeMaxDynamicSharedMemorySize, SM_128_128);
    cudaFuncSetAttribute((const void*)mma_gemm<128,128,2,4,1>, cudaFuncAttributeMaxDynamicSharedMemorySize, SM_128_128);
    cudaFuncSetAttribute((const void*)mma_gemm<128,128,2,4,2>, cudaFuncAttributeMaxDynamicSharedMemorySize, SM_128_128);
    cudaFuncSetAttribute((const void*)mma_gemm<128,96,2,4,0>,  cudaFuncAttributeMaxDynamicSharedMemorySize, SM_128_96);
    cudaFuncSetAttribute((const void*)mma_gemm<128,96,2,4,4>,  cudaFuncAttributeMaxDynamicSharedMemorySize, SM_128_96);
    cudaFuncSetAttribute((const void*)mma_gemm<128,64,2,4,3>,  cudaFuncAttributeMaxDynamicSharedMemorySize, SM_128_64);

    // 0. weight transposes + init
    transpose_k<<<dim3(16,16),256>>>(w_q, wqkvT,            DIMV, DIMV);
    transpose_k<<<dim3(16,16),256>>>(w_k, wqkvT + 512*512,  DIMV, DIMV);
    transpose_k<<<dim3(16,16),256>>>(w_v, wqkvT + 1024*512, DIMV, DIMV);
    transpose_k<<<dim3(16,16),256>>>(w_o, woT,              DIMV, DIMV);
    transpose_k<<<dim3(64,16),256>>>(ff_w1, w1T,            DIMV, FFD);
    transpose_k<<<dim3(16,64),256>>>(ff_w2, w2T,            FFD, DIMV);
    init_kernel<<<72,256>>>(proj);

    // 1. LN1
    ln_kernel<<<NROWS, 256>>>(x, ln1_g, ln1_b, h);

    // 2. fused QKV
    mma_gemm<128,128,2,4,0><<<dim3(QKVD/128, NROWS/128, 1), 256, SM_128_128>>>(
        h, wqkvT, qkv, NROWS, DIMV, DIMV, DIMV, QKVD,
        0,0,0,0,0,0, nullptr,nullptr,nullptr,0,0);

    // 3. kd = k_head @ projDN^T  (fused global max into epilogue)
    mma_gemm<128,96,2,4,4><<<dim3(MP/96, SEQ/128, NB), 256, SM_128_96>>>(
        qkv + DIMV, projDN, kd, SEQ, DHV, QKVD, DHV, MP,
        SAB, DHV, 0,0, 8*SQM, SQM, nullptr,nullptr,nullptr,0,0);

    // 4. kp in place
    expk_kernel<<<(NB*SEQ)/8, 256>>>();

    // 5. kp column sums
    kpsum_kernel<<<dim3(2, NB, 8), 256>>>();

    // 6. ctx = v^T @ kp  (async K-major)
    ctx_gemm<<<dim3(3, 1, NB), 256>>>(qkv + 2*DIMV, kd, ctx);

    // 7. qd = q_head @ projDN^T
    mma_gemm<128,96,2,4,0><<<dim3(MP/96, SEQ/128, NB), 256, SM_128_96>>>(
        qkv, projDN, qd, SEQ, DHV, QKVD, DHV, MP,
        SAB, DHV, 0,0, 8*SQM, SQM, nullptr,nullptr,nullptr,0,0);

    // 8. qp in place + d_inv
    expq_kernel<<<(NB*SEQ)/8, 256>>>();

    // 9. attn = (qp @ ctx^T) * d_inv
    mma_gemm<128,64,2,4,3><<<dim3(1, SEQ/128, NB), 256, SM_128_64>>>(
        qd, ctx, attn, SEQ, MP, MP, MP, DIMV,
        8*SQM, SQM, 8*SCX, SCX, (long long)SEQ*DIMV, DHV,
        nullptr, nullptr, dinv, 8LL*SEQ, SEQ);

    // 10. x1 = x + attn @ w_o + b_o
    mma_gemm<128,128,2,4,1><<<dim3(DIMV/128, NROWS/128, 1), 256, SM_128_128>>>(
        attn, woT, x1, NROWS, DIMV, DIMV, DIMV, DIMV,
        0,0,0,0,0,0, b_o, x, nullptr,0,0);

    // 11. LN2
    ln_kernel<<<NROWS, 256>>>(x1, ln2_g, ln2_b, h);

    // 12. ff1 = gelu(h @ W1 + b1)
    mma_gemm<128,128,2,4,2><<<dim3(FFD/128, NROWS/128, 1), 256, SM_128_128>>>(
        h, w1T, ff1, NROWS, DIMV, DIMV, DIMV, FFD,
        0,0,0,0,0,0, ff_b1, nullptr, nullptr,0,0);

    // 13. out = x1 + ff1 @ W2 + b2
    mma_gemm<128,128,2,4,1><<<dim3(DIMV/128, NROWS/128, 1), 256, SM_128_128>>>(
        ff1, w2T, out, NROWS, FFD, FFD, FFD, DIMV,
        0,0,0,0,0,0, ff_b2, x1, nullptr,0,0);
}

// round 7
// speedup vs baseline: 5.5031x; 1.4500x over previous
#include <cuda_runtime.h>
#include <cuda_fp16.h>
#include <cstdint>
#include <math.h>

#define SEQ   4096
#define BVAL  8
#define DIMV  512
#define HEADS 8
#define DHV   64
#define MF    266
#define MP    288                 /* padded feature dim */
#define NB    (BVAL*HEADS)        /* 64 (b,h) batches */
#define NROWS (BVAL*SEQ)          /* 32768 */
#define FFD   2048
#define QKVD  1536

#define RATIO  0.06131393f        /* 266^-0.5 */
#define DN     0.35355339059327373f
#define KSCALE 256.0f             /* power-of-2 feature scale (cancels exactly) */

// ----------------------------- scratch ------------------------------------
static __device__ __half g_h    [(size_t)NROWS*DIMV];
static __device__ __half g_qkv  [(size_t)NROWS*QKVD];
static __device__ __half g_attn [(size_t)NROWS*DIMV];
static __device__ float  g_x1   [(size_t)NROWS*DIMV];
static __device__ __half g_ff1  [(size_t)NROWS*FFD];
static __device__ float  g_qd   [(size_t)NB*SEQ*MP];   /* dd for queries (fp32) */
static __device__ float  g_kd   [(size_t)NB*SEQ*MP];   /* dd for keys (fp32)    */
static __device__ __half g_qdh  [(size_t)NB*SEQ*MP];   /* qp' = 256*qp          */
static __device__ __half g_kdh  [(size_t)NB*SEQ*MP];   /* kp' = 256*kp          */
static __device__ __half g_projDN[MP*DHV];
static __device__ __half g_wqkvT[QKVD*DIMV];
static __device__ __half g_woT  [DIMV*DIMV];
static __device__ __half g_w1T  [FFD*DIMV];
static __device__ __half g_w2T  [DIMV*FFD];
static __device__ float  g_kpsum[NB*MP];
static __device__ __half g_ctx  [NB*DHV*MP];
static __device__ float  g_dinv [(size_t)NB*SEQ];
static __device__ float  g_kmax;

// ----------------------------- helpers ------------------------------------
__device__ __forceinline__ float wredsum(float v){
    #pragma unroll
    for (int o=16;o;o>>=1) v += __shfl_xor_sync(0xffffffffu, v, o);
    return v;
}
__device__ __forceinline__ float wredmax(float v){
    #pragma unroll
    for (int o=16;o;o>>=1) v = fmaxf(v, __shfl_xor_sync(0xffffffffu, v, o));
    return v;
}
__device__ void atomicMaxF(float* addr, float val){
    int old = __float_as_int(*addr);
    while (__int_as_float(old) < val){
        int prev = atomicCAS((int*)addr, old, __float_as_int(val));
        if (prev == old) break;
        old = prev;
    }
}
__device__ __forceinline__ uint32_t smem_u32(const void* p){
    return (uint32_t)__cvta_generic_to_shared(p);
}

#define CP_ASYNC16(dst, src) \
    asm volatile("cp.async.cg.shared.global [%0], [%1], 16;" :: "r"(dst), "l"(src))
#define CP_COMMIT() asm volatile("cp.async.commit_group;")
#define CP_WAIT1()  asm volatile("cp.async.wait_group 1;")
#define CP_WAIT0()  asm volatile("cp.async.wait_group 0;")

#define CVT_TF32_R(x) asm("cvt.rna.tf32.f32 %0, %0;" : "+r"(x))

#define MMA_TF32(c, a, b) \
    asm volatile("mma.sync.aligned.m16n8k8.row.col.f32.tf32.tf32.f32 " \
        "{%0,%1,%2,%3},{%4,%5,%6,%7},{%8,%9},{%0,%1,%2,%3};" \
        : "+f"((c)[0]),"+f"((c)[1]),"+f"((c)[2]),"+f"((c)[3]) \
        : "r"((a)[0]),"r"((a)[1]),"r"((a)[2]),"r"((a)[3]), \
          "r"((b)[0]),"r"((b)[1]))

#define MMA_F16(c, a, b) \
    asm volatile("mma.sync.aligned.m16n8k16.row.col.f32.f16.f16.f32 " \
        "{%0,%1,%2,%3},{%4,%5,%6,%7},{%8,%9},{%0,%1,%2,%3};" \
        : "+f"((c)[0]),"+f"((c)[1]),"+f"((c)[2]),"+f"((c)[3]) \
        : "r"((a)[0]),"r"((a)[1]),"r"((a)[2]),"r"((a)[3]), \
          "r"((b)[0]),"r"((b)[1]))

// ---------------------------- init / transpose -----------------------------
__global__ void init_kernel(const float* __restrict__ proj){
    int t = blockIdx.x*256 + threadIdx.x;
    if (t == 0) g_kmax = -1e30f;
    if (t < MP*DHV){
        int m = t / DHV, d = t % DHV;
        g_projDN[t] = __float2half((m < MF) ? proj[m*DHV + d] * DN : 0.f);
    }
    if (t < NB*MP) g_kpsum[t] = 0.f;
}

__global__ void transpose_h(const float* __restrict__ in, __half* __restrict__ out, int K, int N){
    __shared__ float t[32][33];
    int k0 = blockIdx.y*32, n0 = blockIdx.x*32;
    int tx = threadIdx.x & 31, ty = threadIdx.x >> 5;
    #pragma unroll
    for (int i=0;i<32;i+=8) t[ty+i][tx] = in[(long long)(k0+ty+i)*N + n0+tx];
    __syncthreads();
    #pragma unroll
    for (int i=0;i<32;i+=8) out[(long long)(n0+ty+i)*K + k0+tx] = __float2half(t[tx][ty+i]);
}

// ----------------------------- layernorm (fp32 in, half out) ---------------
__global__ void ln_kernel(const float* __restrict__ x, const float* __restrict__ g,
                          const float* __restrict__ b, __half* __restrict__ out){
    __shared__ float red[8];
    long long row = blockIdx.x;
    const float* xr = x + row*DIMV;
    int t = threadIdx.x;
    float v0 = xr[t], v1 = xr[t+256];
    float s = wredsum(v0+v1);
    if ((t&31)==0) red[t>>5] = s;
    __syncthreads();
    float mu = 0.f;
    #pragma unroll
    for (int i=0;i<8;i++) mu += red[i];
    mu *= (1.f/DIMV);
    __syncthreads();
    float d0 = v0-mu, d1 = v1-mu;
    float vs = wredsum(d0*d0 + d1*d1);
    if ((t&31)==0) red[t>>5] = vs;
    __syncthreads();
    float var = 0.f;
    #pragma unroll
    for (int i=0;i<8;i++) var += red[i];
    var *= (1.f/DIMV);
    float inv = rsqrtf(var + 1e-5f);
    out[row*DIMV + t]       = __float2half(d0*inv*g[t]     + b[t]);
    out[row*DIMV + t + 256] = __float2half(d1*inv*g[t+256] + b[t+256]);
}

// --------------------------- fp16 mma GEMM ---------------------------------
// D[M,N] = A(MxK half) * B(NxK half)^T, fp32 accumulate.
// EPI: 0 none, 1 bias+res(fp32 out), 2 bias+GELU(half out), 3 row-scale(half out),
//      4 fp32 out + fused global max over cols<MF.
// OUT_HALF selects C element type. Batched via blockIdx.z (z>>3, z&7).
template<int BM,int BN,int BK,int WA_M,int WA_N,int EPI,bool OUT_HALF>
__global__ void __launch_bounds__(256,2) hgemm(
    const __half* __restrict__ A, const __half* __restrict__ B, void* __restrict__ Cv,
    int M, int Kdim, int lda, int ldb, int ldc,
    long long sAo, long long sAi, long long sBo, long long sBi,
    long long sCo, long long sCi,
    const float* __restrict__ bias, const float* __restrict__ res,
    const float* __restrict__ rs, long long sRo, long long sRi)
{
    constexpr int LDH = BK + 8;
    constexpr int WM = BM/WA_M, WN = BN/WA_N;
    constexpr int MFR = WM/16, NFR = WN/8;
    constexpr int CH = BK/8;               // 16B chunks per tile row

    extern __shared__ __half hsm[];
    __half* As = hsm;                      // [2][BM][LDH]
    __half* Bs = hsm + 2*BM*LDH;           // [2][BN][LDH]
    __shared__ float s_red[8];

    int tid = threadIdx.x, lane = tid & 31, wid = tid >> 5;
    int wm = wid % WA_M, wn = wid / WA_M;
    int z = blockIdx.z, zo = z >> 3, zi = z & 7;
    A += (long long)zo*sAo + (long long)zi*sAi;
    B += (long long)zo*sBo + (long long)zi*sBi;
    float*  Cf = (float*) Cv + (OUT_HALF ? 0 : ((long long)zo*sCo + (long long)zi*sCi));
    __half* Ch = (__half*)Cv + (OUT_HALF ? ((long long)zo*sCo + (long long)zi*sCi) : 0);
    const float* rsb = (EPI==3) ? (rs + (long long)zo*sRo + (long long)zi*sRi) : nullptr;

    int m0 = blockIdx.y * BM;
    int n0 = blockIdx.x * BN;

    float acc[MFR][NFR][4];
    #pragma unroll
    for (int i=0;i<MFR;i++)
        #pragma unroll
        for (int j=0;j<NFR;j++)
            #pragma unroll
            for (int q=0;q<4;q++) acc[i][j][q] = 0.f;

    int S = Kdim / BK;
    int tr = lane >> 2, tc = lane & 3;

    auto load_async = [&](int buf, int s){
        int k0 = s*BK;
        #pragma unroll
        for (int i=0;i<BM*CH/256;i++){
            int idx = tid + i*256;
            int row = idx / CH, c = idx % CH;
            uint32_t dst = smem_u32(&As[(buf*BM + row)*LDH + c*8]);
            CP_ASYNC16(dst, A + (long long)(m0+row)*lda + k0 + c*8);
        }
        #pragma unroll
        for (int i=0;i<BN*CH/256;i++){
            int idx = tid + i*256;
            int row = idx / CH, c = idx % CH;
            uint32_t dst = smem_u32(&Bs[(buf*BN + row)*LDH + c*8]);
            CP_ASYNC16(dst, B + (long long)(n0+row)*ldb + k0 + c*8);
        }
    };

    auto compute = [&](int buf){
        #pragma unroll
        for (int kk=0; kk<BK/16; kk++){
            uint32_t af[MFR][4], bf[NFR][2];
            #pragma unroll
            for (int mi=0; mi<MFR; mi++){
                const __half* ap = &As[(buf*BM + wm*WM + mi*16 + tr)*LDH + kk*16 + tc*2];
                af[mi][0] = *(const uint32_t*)(ap);
                af[mi][1] = *(const uint32_t*)(ap + 8*LDH);
                af[mi][2] = *(const uint32_t*)(ap + 8);
                af[mi][3] = *(const uint32_t*)(ap + 8*LDH + 8);
            }
            #pragma unroll
            for (int ni=0; ni<NFR; ni++){
                const __half* bp = &Bs[(buf*BN + wn*WN + ni*8 + tr)*LDH + kk*16 + tc*2];
                bf[ni][0] = *(const uint32_t*)(bp);
                bf[ni][1] = *(const uint32_t*)(bp + 8);
            }
            #pragma unroll
            for (int mi=0; mi<MFR; mi++)
                #pragma unroll
                for (int ni=0; ni<NFR; ni++)
                    MMA_F16(acc[mi][ni], af[mi], bf[ni]);
        }
    };

    load_async(0, 0); CP_COMMIT();
    for (int s=0; s<S; s++){
        if (s+1 < S){ load_async((s+1)&1, s+1); CP_COMMIT(); CP_WAIT1(); }
        else        { CP_WAIT0(); }
        __syncthreads();
        compute(s&1);
        __syncthreads();
    }

    // ---------------- epilogue ----------------
    float tmax = -1e30f;
    #pragma unroll
    for (int mi=0; mi<MFR; mi++){
        #pragma unroll
        for (int ni=0; ni<NFR; ni++){
            int r0 = m0 + wm*WM + mi*16 + tr;
            int c0 = n0 + wn*WN + ni*8 + 2*tc;
            #pragma unroll
            for (int half_=0; half_<2; half_++){
                int r = r0 + half_*8;
                float v0 = acc[mi][ni][half_*2+0];
                float v1 = acc[mi][ni][half_*2+1];
                if (EPI==1){
                    const float* rr = res + (long long)r*ldc + c0;
                    v0 += bias[c0]   + rr[0];
                    v1 += bias[c0+1] + rr[1];
                }
                if (EPI==2){
                    v0 += bias[c0];   v0 = 0.5f*v0*(1.f + erff(v0*0.70710678118654752f));
                    v1 += bias[c0+1]; v1 = 0.5f*v1*(1.f + erff(v1*0.70710678118654752f));
                }
                if (EPI==3){
                    float sc = rsb[r];
                    v0 *= sc; v1 *= sc;
                }
                if (EPI==4){
                    if (c0   < MF) tmax = fmaxf(tmax, v0);
                    if (c0+1 < MF) tmax = fmaxf(tmax, v1);
                }
                if (OUT_HALF)
                    *(__half2*)(Ch + (long long)r*ldc + c0) = __floats2half2_rn(v0, v1);
                else
                    *(float2*)(Cf + (long long)r*ldc + c0) = make_float2(v0, v1);
            }
        }
    }
    if (EPI==4){
        tmax = wredmax(tmax);
        if (lane==0) s_red[wid] = tmax;
        __syncthreads();
        if (tid==0){
            float m2 = s_red[0];
            #pragma unroll
            for (int i=1;i<8;i++) m2 = fmaxf(m2, s_red[i]);
            atomicMaxF(&g_kmax, m2);
        }
    }
}

// --------------------- ctx GEMM: ctx[64,288] = v^T @ kp' -------------------
// A = v slice of qkv (half, [4096][64] stride QKVD); B = kp' (half, [4096][MP]).
// fp32 smem K-major tiles, tf32 mma, register-staged prefetch.
__global__ void __launch_bounds__(256) ctx_gemm(
    const __half* __restrict__ Abase, const __half* __restrict__ Bbase,
    __half* __restrict__ Cbase)
{
    constexpr int BK=32, LDM=72, LDN=104;
    __shared__ float As[BK][LDM];
    __shared__ float Bs[BK][LDN];

    int tid = threadIdx.x, lane = tid & 31, wid = tid >> 5;
    int wm = wid & 1, wn = wid >> 1;          // WM=32, WN=24
    int tr = lane >> 2, tc = lane & 3;
    int z = blockIdx.z, zo = z >> 3, zi = z & 7;
    const __half* A = Abase + (long long)zo*SEQ*QKVD + zi*DHV;
    const __half* B = Bbase + (long long)z*SEQ*MP;
    __half* C = Cbase + (long long)z*DHV*MP;
    int n0 = blockIdx.x * 96;

    float acc[2][3][4];
    #pragma unroll
    for (int i=0;i<2;i++)
        #pragma unroll
        for (int j=0;j<3;j++)
            #pragma unroll
            for (int q=0;q<4;q++) acc[i][j][q] = 0.f;

    // per-thread staging: A one 8-half chunk, B two 8-half chunks
    int ar = tid >> 3, ac = tid & 7;                 // A: 32 rows x 8 chunks
    int br0 = tid / 12, bc0 = tid % 12;              // B: 32 rows x 12 chunks (384)
    int idx2 = tid + 256;
    int br1 = idx2 / 12, bc1 = idx2 % 12;
    bool hasB1 = idx2 < 384;

    uint4 rA, rB0, rB1;
    auto fetch = [&](int s){
        int k0 = s*BK;
        rA  = *(const uint4*)(A + (long long)(k0+ar)*QKVD + ac*8);
        rB0 = *(const uint4*)(B + (long long)(k0+br0)*MP + n0 + bc0*8);
        if (hasB1) rB1 = *(const uint4*)(B + (long long)(k0+br1)*MP + n0 + bc1*8);
    };
    auto stage = [&](){
        const __half* ha = (const __half*)&rA;
        #pragma unroll
        for (int j=0;j<8;j++) As[ar][ac*8+j] = __half2float(ha[j]);
        const __half* hb = (const __half*)&rB0;
        #pragma unroll
        for (int j=0;j<8;j++) Bs[br0][bc0*8+j] = __half2float(hb[j]);
        if (hasB1){
            const __half* hb1 = (const __half*)&rB1;
            #pragma unroll
            for (int j=0;j<8;j++) Bs[br1][bc1*8+j] = __half2float(hb1[j]);
        }
    };
    auto compute = [&](){
        #pragma unroll
        for (int kk=0; kk<4; kk++){
            uint32_t af[2][4], bf[3][2];
            #pragma unroll
            for (int mi=0; mi<2; mi++){
                int m = wm*32 + mi*16 + tr;
                af[mi][0] = __float_as_uint(As[kk*8+tc  ][m]);
                af[mi][1] = __float_as_uint(As[kk*8+tc  ][m+8]);
                af[mi][2] = __float_as_uint(As[kk*8+tc+4][m]);
                af[mi][3] = __float_as_uint(As[kk*8+tc+4][m+8]);
                CVT_TF32_R(af[mi][0]); CVT_TF32_R(af[mi][1]);
                CVT_TF32_R(af[mi][2]); CVT_TF32_R(af[mi][3]);
            }
            #pragma unroll
            for (int ni=0; ni<3; ni++){
                int n = wn*24 + ni*8 + tr;
                bf[ni][0] = __float_as_uint(Bs[kk*8+tc  ][n]);
                bf[ni][1] = __float_as_uint(Bs[kk*8+tc+4][n]);
                CVT_TF32_R(bf[ni][0]); CVT_TF32_R(bf[ni][1]);
            }
            #pragma unroll
            for (int mi=0; mi<2; mi++)
                #pragma unroll
                for (int ni=0; ni<3; ni++)
                    MMA_TF32(acc[mi][ni], af[mi], bf[ni]);
        }
    };

    const int S = SEQ/BK;      // 128
    fetch(0);
    for (int s=0; s<S; s++){
        stage();
        __syncthreads();
        if (s+1 < S) fetch(s+1);   // LDG latency overlaps compute
        compute();
        __syncthreads();
    }

    #pragma unroll
    for (int mi=0; mi<2; mi++){
        #pragma unroll
        for (int ni=0; ni<3; ni++){
            int r0 = wm*32 + mi*16 + tr;
            int c0 = n0 + wn*24 + ni*8 + 2*tc;
            #pragma unroll
            for (int half_=0; half_<2; half_++){
                int r = r0 + half_*8;
                *(__half2*)(C + (long long)r*MP + c0) =
                    __floats2half2_rn(acc[mi][ni][half_*2+0], acc[mi][ni][half_*2+1]);
            }
        }
    }
}

// ---------------------- key features: kp' = 256*kp -------------------------
__global__ void expk_kernel(){
    int warp = threadIdx.x>>5, lane = threadIdx.x&31;
    long long row = (long long)blockIdx.x*8 + warp;
    int batch = (int)(row >> 12);
    int n = (int)(row & 4095);
    int b = batch>>3, hh = batch&7;
    const __half* kr = g_qkv + ((long long)b*SEQ + n)*QKVD + DIMV + hh*DHV;
    float a0 = __half2float(kr[lane]), a1 = __half2float(kr[lane+32]);
    float diag = 0.0625f * wredsum(a0*a0 + a1*a1);
    float mx = g_kmax;
    const float* dd = g_kd + row*MP;
    __half* oo = g_kdh + row*MP;
    #pragma unroll
    for (int i=0;i<9;i++){
        int m = lane + i*32;
        float o = 0.f;
        if (m < MF) o = KSCALE * RATIO * (expf(dd[m] - diag - mx) + 1e-4f);
        oo[m] = __float2half(o);
    }
}

// ------------------ query features qp' = 256*qp + d_inv --------------------
__global__ void expq_kernel(){
    int warp = threadIdx.x>>5, lane = threadIdx.x&31;
    long long row = (long long)blockIdx.x*8 + warp;
    int batch = (int)(row >> 12);
    int n = (int)(row & 4095);
    int b = batch>>3, hh = batch&7;
    const __half* qr = g_qkv + ((long long)b*SEQ + n)*QKVD + hh*DHV;
    float a0 = __half2float(qr[lane]), a1 = __half2float(qr[lane+32]);
    float diag = 0.0625f * wredsum(a0*a0 + a1*a1);
    const float* dd = g_qd + row*MP;
    __half* oo = g_qdh + row*MP;
    float vals[9];
    float mx = -1e30f;
    #pragma unroll
    for (int i=0;i<9;i++){
        int m = lane + i*32;
        vals[i] = dd[m];
        if (m < MF) mx = fmaxf(mx, vals[i]);
    }
    mx = wredmax(mx);
    const float* kps = g_kpsum + batch*MP;
    float dp = 0.f;
    #pragma unroll
    for (int i=0;i<9;i++){
        int m = lane + i*32;
        float p = 0.f;
        if (m < MF){
            p = KSCALE * RATIO * (expf(vals[i] - diag - mx) + 1e-4f);
            dp += p * kps[m];
        }
        oo[m] = __float2half(p);
    }
    dp = wredsum(dp);
    if (lane == 0) g_dinv[row] = 1.f / dp;   // scales cancel: qp'*ctx' * 1/(qp'*kps')
}

// ------------------------- kp' column sums ---------------------------------
__global__ void kpsum_kernel(){
    int m = blockIdx.x*256 + threadIdx.x;
    int batch = blockIdx.y;
    int nchunk = blockIdx.z;
    if (m >= MP) return;
    const __half* p = g_kdh + (long long)batch*SEQ*MP + (long long)nchunk*512*MP + m;
    float s = 0.f;
    #pragma unroll 4
    for (int n=0; n<512; n++) s += __half2float(p[(long long)n*MP]);
    atomicAdd(&g_kpsum[batch*MP + m], s);
}

// ----------------------------- launch -------------------------------------
extern "C" void kernel_launch(void* const* d_in, const int* in_sizes, int n_in,
                              void* d_out, int out_size){
    const float* x     = (const float*)d_in[0];
    const float* w_q   = (const float*)d_in[1];
    const float* w_k   = (const float*)d_in[2];
    const float* w_v   = (const float*)d_in[3];
    const float* w_o   = (const float*)d_in[4];
    const float* b_o   = (const float*)d_in[5];
    const float* ln1_g = (const float*)d_in[6];
    const float* ln1_b = (const float*)d_in[7];
    const float* ln2_g = (const float*)d_in[8];
    const float* ln2_b = (const float*)d_in[9];
    const float* ff_w1 = (const float*)d_in[10];
    const float* ff_b1 = (const float*)d_in[11];
    const float* ff_w2 = (const float*)d_in[12];
    const float* ff_b2 = (const float*)d_in[13];
    const float* proj  = (const float*)d_in[14];
    float* out = (float*)d_out;

    __half *h,*qkv,*attn,*ff1,*qdh,*kdh,*projDN,*wqkvT,*woT,*w1T,*w2T,*ctx;
    float *x1,*qd,*kd,*dinv;
    cudaGetSymbolAddress((void**)&h,     g_h);
    cudaGetSymbolAddress((void**)&qkv,   g_qkv);
    cudaGetSymbolAddress((void**)&attn,  g_attn);
    cudaGetSymbolAddress((void**)&x1,    g_x1);
    cudaGetSymbolAddress((void**)&ff1,   g_ff1);
    cudaGetSymbolAddress((void**)&qd,    g_qd);
    cudaGetSymbolAddress((void**)&kd,    g_kd);
    cudaGetSymbolAddress((void**)&qdh,   g_qdh);
    cudaGetSymbolAddress((void**)&kdh,   g_kdh);
    cudaGetSymbolAddress((void**)&projDN,g_projDN);
    cudaGetSymbolAddress((void**)&wqkvT, g_wqkvT);
    cudaGetSymbolAddress((void**)&woT,   g_woT);
    cudaGetSymbolAddress((void**)&w1T,   g_w1T);
    cudaGetSymbolAddress((void**)&w2T,   g_w2T);
    cudaGetSymbolAddress((void**)&ctx,   g_ctx);
    cudaGetSymbolAddress((void**)&dinv,  g_dinv);

    const long long SQM = (long long)SEQ*MP;
    const long long SCX = (long long)DHV*MP;
    const long long SAB = (long long)SEQ*QKVD;

    // smem = (2*BM + 2*BN)*(BK+8)*2 bytes
    const int SM_128_128_64 = (2*128+2*128)*(64+8)*2;  // 73728
    const int SM_128_96_64  = (2*128+2*96 )*(64+8)*2;  // 64512
    const int SM_128_64_32  = (2*128+2*64 )*(32+8)*2;  // 30720
    cudaFuncSetAttribute((const void*)hgemm<128,128,64,2,4,0,true >, cudaFuncAttributeMaxDynamicSharedMemorySize, SM_128_128_64);
    cudaFuncSetAttribute((const void*)hgemm<128,128,64,2,4,1,false>, cudaFuncAttributeMaxDynamicSharedMemorySize, SM_128_128_64);
    cudaFuncSetAttribute((const void*)hgemm<128,128,64,2,4,2,true >, cudaFuncAttributeMaxDynamicSharedMemorySize, SM_128_128_64);
    cudaFuncSetAttribute((const void*)hgemm<128,96,64,2,4,0,false>,  cudaFuncAttributeMaxDynamicSharedMemorySize, SM_128_96_64);
    cudaFuncSetAttribute((const void*)hgemm<128,96,64,2,4,4,false>,  cudaFuncAttributeMaxDynamicSharedMemorySize, SM_128_96_64);
    cudaFuncSetAttribute((const void*)hgemm<128,64,32,2,4,3,true >,  cudaFuncAttributeMaxDynamicSharedMemorySize, SM_128_64_32);

    // 0. weight transposes (fp32 -> half) + init
    transpose_h<<<dim3(16,16),256>>>(w_q, wqkvT,            DIMV, DIMV);
    transpose_h<<<dim3(16,16),256>>>(w_k, wqkvT + 512*512,  DIMV, DIMV);
    transpose_h<<<dim3(16,16),256>>>(w_v, wqkvT + 1024*512, DIMV, DIMV);
    transpose_h<<<dim3(16,16),256>>>(w_o, woT,              DIMV, DIMV);
    transpose_h<<<dim3(64,16),256>>>(ff_w1, w1T,            DIMV, FFD);
    transpose_h<<<dim3(16,64),256>>>(ff_w2, w2T,            FFD, DIMV);
    init_kernel<<<72,256>>>(proj);

    // 1. LN1 (fp32 -> half)
    ln_kernel<<<NROWS, 256>>>(x, ln1_g, ln1_b, h);

    // 2. fused QKV (half out)
    hgemm<128,128,64,2,4,0,true><<<dim3(QKVD/128, NROWS/128, 1), 256, SM_128_128_64>>>(
        h, wqkvT, qkv, NROWS, DIMV, DIMV, DIMV, QKVD,
        0,0,0,0,0,0, nullptr,nullptr,nullptr,0,0);

    // 3. kd = k_head @ projDN^T (fp32 dd out, fused global max)
    hgemm<128,96,64,2,4,4,false><<<dim3(MP/96, SEQ/128, NB), 256, SM_128_96_64>>>(
        qkv + DIMV, projDN, kd, SEQ, DHV, QKVD, DHV, MP,
        SAB, DHV, 0,0, 8*SQM, SQM, nullptr,nullptr,nullptr,0,0);

    // 4. kp' (half, x256)
    expk_kernel<<<(NB*SEQ)/8, 256>>>();

    // 5. kp' column sums (fp32)
    kpsum_kernel<<<dim3(2, NB, 8), 256>>>();

    // 6. ctx' = v^T @ kp' (half out)
    ctx_gemm<<<dim3(3, 1, NB), 256>>>(qkv + 2*DIMV, kdh, ctx);

    // 7. qd = q_head @ projDN^T (fp32 dd out)
    hgemm<128,96,64,2,4,0,false><<<dim3(MP/96, SEQ/128, NB), 256, SM_128_96_64>>>(
        qkv, projDN, qd, SEQ, DHV, QKVD, DHV, MP,
        SAB, DHV, 0,0, 8*SQM, SQM, nullptr,nullptr,nullptr,0,0);

    // 8. qp' (half, x256) + d_inv
    expq_kernel<<<(NB*SEQ)/8, 256>>>();

    // 9. attn = (qp' @ ctx'^T) * d_inv (half out, head-concat)
    hgemm<128,64,32,2,4,3,true><<<dim3(1, SEQ/128, NB), 256, SM_128_64_32>>>(
        qdh, ctx, attn, SEQ, MP, MP, MP, DIMV,
        8*SQM, SQM, 8*SCX, SCX, (long long)SEQ*DIMV, DHV,
        nullptr, nullptr, dinv, 8LL*SEQ, SEQ);

    // 10. x1 = x + attn @ w_o + b_o (fp32 out)
    hgemm<128,128,64,2,4,1,false><<<dim3(DIMV/128, NROWS/128, 1), 256, SM_128_128_64>>>(
        attn, woT, x1, NROWS, DIMV, DIMV, DIMV, DIMV,
        0,0,0,0,0,0, b_o, x, nullptr,0,0);

    // 11. LN2 (fp32 -> half, reuse h)
    ln_kernel<<<NROWS, 256>>>(x1, ln2_g, ln2_b, h);

    // 12. ff1 = gelu(h @ W1 + b1) (half out)
    hgemm<128,128,64,2,4,2,true><<<dim3(FFD/128, NROWS/128, 1), 256, SM_128_128_64>>>(
        h, w1T, ff1, NROWS, DIMV, DIMV, DIMV, FFD,
        0,0,0,0,0,0, ff_b1, nullptr, nullptr,0,0);

    // 13. out = x1 + ff1 @ W2 + b2 (fp32 out)
    hgemm<128,128,64,2,4,1,false><<<dim3(DIMV/128, NROWS/128, 1), 256, SM_128_128_64>>>(
        ff1, w2T, out, NROWS, FFD, FFD, FFD, DIMV,
        0,0,0,0,0,0, ff_b2, x1, nullptr,0,0);
}